// round 1
// baseline (speedup 1.0000x reference)
#include <cuda_runtime.h>
#include <math.h>

#define VOCABN 96
#define DIM 1024
#define NH 16
#define HSZ 64
#define NL 8
#define BATCH 8
#define SEQ 1024
#define FFD 4096
#define MROWS (BATCH*SEQ)   // 8192

// ---------------- scratch (device globals; no allocations allowed) ----------
__device__ float g_x[MROWS*DIM];
__device__ float g_q[MROWS*DIM];
__device__ float g_k[MROWS*DIM];
__device__ float g_v[MROWS*DIM];
__device__ float g_o[MROWS*DIM];
__device__ float g_y[MROWS*DIM];
__device__ float g_h[(long long)MROWS*FFD];
__device__ float g_wei[(long long)BATCH*NH*SEQ*SEQ];   // 512 MB
__device__ float g_wq[NL*DIM*DIM];
__device__ float g_wk[NL*DIM*DIM];
__device__ float g_wv[NL*DIM*DIM];
__device__ float g_nll[MROWS];

// ---------------- repack Wq/Wk/Wv: [L,H,D,HS] -> [L, D, H*HS] ---------------
__global__ void repack_qkv_kernel(const float* __restrict__ Wq,
                                  const float* __restrict__ Wk,
                                  const float* __restrict__ Wv) {
    long long i = (long long)blockIdx.x * blockDim.x + threadIdx.x;
    if (i >= (long long)NL * DIM * DIM) return;
    int e = (int)(i % HSZ);
    long long rem = i / HSZ;
    int d = (int)(rem % DIM); rem /= DIM;
    int h = (int)(rem % NH);
    int l = (int)(rem / NH);
    long long dst = ((long long)l * DIM + d) * DIM + h * HSZ + e;
    g_wq[dst] = Wq[i];
    g_wk[dst] = Wk[i];
    g_wv[dst] = Wv[i];
}

// ---------------- embedding: x = tok_emb[index] + pos_emb[:T] ---------------
__global__ void embed_kernel(const int* __restrict__ index,
                             const float* __restrict__ tok,
                             const float* __restrict__ pos) {
    int i = blockIdx.x * blockDim.x + threadIdx.x;
    if (i >= MROWS * DIM) return;
    int d = i % DIM;
    int bt = i / DIM;
    int t = bt % SEQ;
    g_x[i] = tok[(long long)index[bt] * DIM + d] + pos[(long long)t * DIM + d];
}

// ---------------- generic batched SGEMM: C = A @ B (+bias)(+relu) -----------
// per-z offsets: off = (z / zdiv) * s1 + (z % zdiv) * s2  (lets the attention
// output GEMM scatter heads into the concat layout directly)
#define BM 64
#define BN 64
#define BKK 16

__global__ __launch_bounds__(256)
void gemm_kernel(const float* __restrict__ A, const float* __restrict__ Bm,
                 const float* __restrict__ bias, float* __restrict__ C,
                 int M, int N, int K, int lda, int ldb, int ldc, int zdiv,
                 long long sA1, long long sA2,
                 long long sB1, long long sB2,
                 long long sC1, long long sC2, int relu)
{
    int z = blockIdx.z;
    int z1 = z / zdiv, z2 = z % zdiv;
    A  += z1 * sA1 + z2 * sA2;
    Bm += z1 * sB1 + z2 * sB2;
    C  += z1 * sC1 + z2 * sC2;

    int bm = blockIdx.y * BM;
    int bn = blockIdx.x * BN;
    __shared__ float As[BKK][BM + 1];
    __shared__ float Bs[BKK][BN + 1];

    int tid = threadIdx.x;
    int tx = tid & 15, ty = tid >> 4;
    float acc[4][4] = {};

    for (int k0 = 0; k0 < K; k0 += BKK) {
        #pragma unroll
        for (int i = 0; i < 4; i++) {
            int idx = tid + i * 256;          // 0..1023
            int m  = idx >> 4;                // 0..63
            int kk = idx & 15;                // 0..15
            int gm = bm + m;
            float v = 0.f;
            if (gm < M) v = A[(long long)gm * lda + (k0 + kk)];
            As[kk][m] = v;
        }
        #pragma unroll
        for (int i = 0; i < 4; i++) {
            int idx = tid + i * 256;
            int kk = idx >> 6;                // 0..15
            int n  = idx & 63;                // 0..63
            int gn = bn + n;
            float v = 0.f;
            if (gn < N) v = Bm[(long long)(k0 + kk) * ldb + gn];
            Bs[kk][n] = v;
        }
        __syncthreads();
        #pragma unroll
        for (int kk = 0; kk < BKK; kk++) {
            float a[4], b[4];
            #pragma unroll
            for (int i = 0; i < 4; i++) a[i] = As[kk][ty * 4 + i];
            #pragma unroll
            for (int j = 0; j < 4; j++) b[j] = Bs[kk][tx * 4 + j];
            #pragma unroll
            for (int i = 0; i < 4; i++)
                #pragma unroll
                for (int j = 0; j < 4; j++)
                    acc[i][j] += a[i] * b[j];
        }
        __syncthreads();
    }

    #pragma unroll
    for (int i = 0; i < 4; i++) {
        int gm = bm + ty * 4 + i;
        if (gm >= M) continue;
        #pragma unroll
        for (int j = 0; j < 4; j++) {
            int gn = bn + tx * 4 + j;
            if (gn >= N) continue;
            float v = acc[i][j];
            if (bias) v += bias[gn];
            if (relu) v = fmaxf(v, 0.f);
            C[(long long)gm * ldc + gn] = v;
        }
    }
}

// ---------------- causal scores: wei = scale * Q @ K^T, mask -1e9 -----------
__global__ __launch_bounds__(256)
void scores_kernel() {
    int z = blockIdx.z;                    // b*NH + h
    int b = z / NH, h = z % NH;
    const float* Q  = g_q + (long long)b * SEQ * DIM + h * HSZ;
    const float* Kp = g_k + (long long)b * SEQ * DIM + h * HSZ;
    float* C = g_wei + (long long)z * SEQ * SEQ;

    int t0 = blockIdx.y * 64;
    int s0 = blockIdx.x * 64;
    int tid = threadIdx.x;
    int tx = tid & 15, ty = tid >> 4;

    if (s0 > t0 + 63) {                    // tile fully above diagonal
        #pragma unroll
        for (int i = 0; i < 4; i++)
            #pragma unroll
            for (int j = 0; j < 4; j++)
                C[(long long)(t0 + ty * 4 + i) * SEQ + (s0 + tx * 4 + j)] = -1e9f;
        return;
    }

    __shared__ float Qs[16][65];
    __shared__ float Ks[16][65];
    float acc[4][4] = {};

    for (int k0 = 0; k0 < HSZ; k0 += 16) {
        #pragma unroll
        for (int i = 0; i < 4; i++) {
            int idx = tid + i * 256;
            int m  = idx >> 4;
            int kk = idx & 15;
            Qs[kk][m] = Q[(long long)(t0 + m) * DIM + (k0 + kk)];
            Ks[kk][m] = Kp[(long long)(s0 + m) * DIM + (k0 + kk)];
        }
        __syncthreads();
        #pragma unroll
        for (int kk = 0; kk < 16; kk++) {
            float a[4], bb[4];
            #pragma unroll
            for (int i = 0; i < 4; i++) a[i] = Qs[kk][ty * 4 + i];
            #pragma unroll
            for (int j = 0; j < 4; j++) bb[j] = Ks[kk][tx * 4 + j];
            #pragma unroll
            for (int i = 0; i < 4; i++)
                #pragma unroll
                for (int j = 0; j < 4; j++)
                    acc[i][j] += a[i] * bb[j];
        }
        __syncthreads();
    }

    const float scale = 0.125f;            // 1/sqrt(64)
    #pragma unroll
    for (int i = 0; i < 4; i++) {
        int t = t0 + ty * 4 + i;
        #pragma unroll
        for (int j = 0; j < 4; j++) {
            int s = s0 + tx * 4 + j;
            C[(long long)t * SEQ + s] = (s <= t) ? acc[i][j] * scale : -1e9f;
        }
    }
}

// ---------------- row softmax over T=1024 -----------------------------------
__global__ __launch_bounds__(256)
void softmax_kernel() {
    long long row = blockIdx.x;
    float* p = g_wei + row * SEQ;
    __shared__ float red[256];
    int tid = threadIdx.x;

    float v[4];
    float m = -1e30f;
    #pragma unroll
    for (int i = 0; i < 4; i++) { v[i] = p[tid + i * 256]; m = fmaxf(m, v[i]); }
    red[tid] = m; __syncthreads();
    for (int s = 128; s > 0; s >>= 1) {
        if (tid < s) red[tid] = fmaxf(red[tid], red[tid + s]);
        __syncthreads();
    }
    m = red[0]; __syncthreads();

    float sum = 0.f;
    #pragma unroll
    for (int i = 0; i < 4; i++) { v[i] = expf(v[i] - m); sum += v[i]; }
    red[tid] = sum; __syncthreads();
    for (int s = 128; s > 0; s >>= 1) {
        if (tid < s) red[tid] += red[tid + s];
        __syncthreads();
    }
    float inv = 1.f / red[0];
    #pragma unroll
    for (int i = 0; i < 4; i++) p[tid + i * 256] = v[i] * inv;
}

// ---------------- x = LayerNorm(x (+ y)) * g + b ----------------------------
__global__ __launch_bounds__(256)
void add_ln_kernel(float* __restrict__ x, const float* __restrict__ y,
                   const float* __restrict__ g, const float* __restrict__ bb) {
    int row = blockIdx.x;
    float* xr = x + (long long)row * DIM;
    const float* yr = y ? y + (long long)row * DIM : nullptr;
    __shared__ float s[DIM];
    __shared__ float red[256];
    int tid = threadIdx.x;

    float local = 0.f;
    #pragma unroll
    for (int i = 0; i < 4; i++) {
        int d = tid + i * 256;
        float v = xr[d];
        if (yr) v += yr[d];
        s[d] = v;
        local += v;
    }
    red[tid] = local; __syncthreads();
    for (int st = 128; st > 0; st >>= 1) {
        if (tid < st) red[tid] += red[tid + st];
        __syncthreads();
    }
    float mean = red[0] * (1.0f / DIM); __syncthreads();

    local = 0.f;
    #pragma unroll
    for (int i = 0; i < 4; i++) {
        float d2 = s[tid + i * 256] - mean;
        local += d2 * d2;
    }
    red[tid] = local; __syncthreads();
    for (int st = 128; st > 0; st >>= 1) {
        if (tid < st) red[tid] += red[tid + st];
        __syncthreads();
    }
    float inv = rsqrtf(red[0] * (1.0f / DIM) + 1e-5f);
    #pragma unroll
    for (int i = 0; i < 4; i++) {
        int d = tid + i * 256;
        xr[d] = (s[d] - mean) * inv * g[d] + bb[d];
    }
}

// ---------------- per-row NLL from logits (V=96) -----------------------------
__global__ __launch_bounds__(128)
void nll_kernel(const float* __restrict__ logits, const int* __restrict__ targets) {
    int row = blockIdx.x;
    const float* p = logits + (long long)row * VOCABN;
    __shared__ float red[128];
    int tid = threadIdx.x;

    float v = (tid < VOCABN) ? p[tid] : -1e30f;
    red[tid] = v; __syncthreads();
    for (int s = 64; s > 0; s >>= 1) {
        if (tid < s) red[tid] = fmaxf(red[tid], red[tid + s]);
        __syncthreads();
    }
    float m = red[0]; __syncthreads();

    float e = (tid < VOCABN) ? expf(v - m) : 0.f;
    red[tid] = e; __syncthreads();
    for (int s = 64; s > 0; s >>= 1) {
        if (tid < s) red[tid] += red[tid + s];
        __syncthreads();
    }
    if (tid == 0) {
        float lse = m + logf(red[0]);
        g_nll[row] = lse - p[targets[row]];
    }
}

__global__ __launch_bounds__(256)
void loss_kernel(float* __restrict__ out) {
    __shared__ float red[256];
    int tid = threadIdx.x;
    float s = 0.f;
    for (int i = tid; i < MROWS; i += 256) s += g_nll[i];
    red[tid] = s; __syncthreads();
    for (int st = 128; st > 0; st >>= 1) {
        if (tid < st) red[tid] += red[tid + st];
        __syncthreads();
    }
    if (tid == 0) out[0] = red[0] * (1.0f / MROWS);
}

// ---------------- host-side launch helpers ----------------------------------
static float* sym(const void* s) {
    void* p = nullptr;
    cudaGetSymbolAddress(&p, s);
    return (float*)p;
}

static void run_gemm(const float* A, const float* B, const float* bias, float* C,
                     int M, int N, int K, int lda, int ldb, int ldc,
                     int gz, int zdiv,
                     long long sA1, long long sA2,
                     long long sB1, long long sB2,
                     long long sC1, long long sC2, int relu) {
    dim3 grid((N + BN - 1) / BN, (M + BM - 1) / BM, gz);
    gemm_kernel<<<grid, 256>>>(A, B, bias, C, M, N, K, lda, ldb, ldc, zdiv,
                               sA1, sA2, sB1, sB2, sC1, sC2, relu);
}

extern "C" void kernel_launch(void* const* d_in, const int* in_sizes, int n_in,
                              void* d_out, int out_size) {
    const int*   index   = (const int*)  d_in[0];
    const int*   targets = (const int*)  d_in[1];
    const float* tok     = (const float*)d_in[2];
    const float* pos     = (const float*)d_in[3];
    const float* Wq      = (const float*)d_in[4];
    const float* Wk      = (const float*)d_in[5];
    const float* Wv      = (const float*)d_in[6];
    const float* Wo      = (const float*)d_in[7];
    const float* bo      = (const float*)d_in[8];
    const float* W1      = (const float*)d_in[9];
    const float* b1      = (const float*)d_in[10];
    const float* W2      = (const float*)d_in[11];
    const float* b2      = (const float*)d_in[12];
    const float* ln1g    = (const float*)d_in[13];
    const float* ln1b    = (const float*)d_in[14];
    const float* ln2g    = (const float*)d_in[15];
    const float* ln2b    = (const float*)d_in[16];
    const float* lnfg    = (const float*)d_in[17];
    const float* lnfb    = (const float*)d_in[18];
    const float* Wlm     = (const float*)d_in[19];
    const float* blm     = (const float*)d_in[20];
    float* out = (float*)d_out;

    float* x  = sym(g_x);
    float* q  = sym(g_q);
    float* k  = sym(g_k);
    float* v  = sym(g_v);
    float* o  = sym(g_o);
    float* y  = sym(g_y);
    float* hb = sym(g_h);
    float* wq = sym(g_wq);
    float* wk = sym(g_wk);
    float* wv = sym(g_wv);

    // repack per-head QKV weights into plain [D, D] matrices per layer
    {
        long long n = (long long)NL * DIM * DIM;
        int grid = (int)((n + 255) / 256);
        repack_qkv_kernel<<<grid, 256>>>(Wq, Wk, Wv);
    }

    // embedding
    {
        int n = MROWS * DIM;
        embed_kernel<<<(n + 255) / 256, 256>>>(index, tok, pos);
    }

    for (int l = 0; l < NL; l++) {
        const float* wq_l = wq + (long long)l * DIM * DIM;
        const float* wk_l = wk + (long long)l * DIM * DIM;
        const float* wv_l = wv + (long long)l * DIM * DIM;
        const float* wo_l = Wo + (long long)l * DIM * DIM;
        const float* bo_l = bo + (long long)l * DIM;
        const float* w1_l = W1 + (long long)l * DIM * FFD;
        const float* b1_l = b1 + (long long)l * FFD;
        const float* w2_l = W2 + (long long)l * FFD * DIM;
        const float* b2_l = b2 + (long long)l * DIM;

        // q/k/v projections: [8192,1024] = x @ W
        run_gemm(x, wq_l, nullptr, q, MROWS, DIM, DIM, DIM, DIM, DIM,
                 1, 1, 0, 0, 0, 0, 0, 0, 0);
        run_gemm(x, wk_l, nullptr, k, MROWS, DIM, DIM, DIM, DIM, DIM,
                 1, 1, 0, 0, 0, 0, 0, 0, 0);
        run_gemm(x, wv_l, nullptr, v, MROWS, DIM, DIM, DIM, DIM, DIM,
                 1, 1, 0, 0, 0, 0, 0, 0, 0);

        // causal attention scores + softmax
        {
            dim3 grid(SEQ / 64, SEQ / 64, BATCH * NH);
            scores_kernel<<<grid, 256>>>();
        }
        softmax_kernel<<<BATCH * NH * SEQ, 256>>>();

        // attention output: per (b,h)  O_bh = P_bh @ V_bh, heads written into
        // concat layout of g_o directly.  z = b*NH + h
        run_gemm(sym(g_wei), v, nullptr, o,
                 SEQ, HSZ, SEQ, SEQ, DIM, DIM,
                 BATCH * NH, NH,
                 (long long)NH * SEQ * SEQ, (long long)SEQ * SEQ,   // A: wei
                 (long long)SEQ * DIM,      (long long)HSZ,         // B: v
                 (long long)SEQ * DIM,      (long long)HSZ,         // C: o
                 0);

        // output projection + residual LN
        run_gemm(o, wo_l, bo_l, y, MROWS, DIM, DIM, DIM, DIM, DIM,
                 1, 1, 0, 0, 0, 0, 0, 0, 0);
        add_ln_kernel<<<MROWS, 256>>>(x, y, ln1g + (long long)l * DIM,
                                            ln1b + (long long)l * DIM);

        // feed-forward + residual LN
        run_gemm(x, w1_l, b1_l, hb, MROWS, FFD, DIM, DIM, FFD, FFD,
                 1, 1, 0, 0, 0, 0, 0, 0, 1);
        run_gemm(hb, w2_l, b2_l, y, MROWS, DIM, FFD, FFD, DIM, DIM,
                 1, 1, 0, 0, 0, 0, 0, 0, 0);
        add_ln_kernel<<<MROWS, 256>>>(x, y, ln2g + (long long)l * DIM,
                                            ln2b + (long long)l * DIM);
    }

    // final LN (no residual)
    add_ln_kernel<<<MROWS, 256>>>(x, nullptr, lnfg, lnfb);

    // logits = xf @ Wlm + blm  -> straight into d_out
    run_gemm(x, Wlm, blm, out, MROWS, VOCABN, DIM, DIM, VOCABN, VOCABN,
             1, 1, 0, 0, 0, 0, 0, 0, 0);

    // loss
    nll_kernel<<<MROWS, 128>>>(out, targets);
    if (out_size > MROWS * VOCABN) {
        loss_kernel<<<1, 256>>>(out + (long long)MROWS * VOCABN);
    }
}

// round 3
// speedup vs baseline: 2.4595x; 2.4595x over previous
#include <cuda_runtime.h>
#include <math.h>
#include <stdint.h>

#define VOCABN 96
#define DIM 1024
#define NH 16
#define HSZ 64
#define NL 8
#define BATCH 8
#define SEQ 1024
#define FFD 4096
#define MROWS (BATCH*SEQ)   // 8192

// ---------------- scratch (device globals; no allocations allowed) ----------
__device__ float g_x[MROWS*DIM];
__device__ float g_q[MROWS*DIM];
__device__ float g_k[MROWS*DIM];
__device__ float g_v[MROWS*DIM];
__device__ float g_o[MROWS*DIM];
__device__ float g_y[MROWS*DIM];
__device__ float g_h[(long long)MROWS*FFD];
__device__ float g_wei[(long long)BATCH*NH*SEQ*SEQ];   // 512 MB
__device__ float g_wqT[NL*DIM*DIM];
__device__ float g_wkT[NL*DIM*DIM];
__device__ float g_wvT[NL*DIM*DIM];
__device__ float g_woT[NL*DIM*DIM];
__device__ float g_w1T[(long long)NL*DIM*FFD];
__device__ float g_w2T[(long long)NL*FFD*DIM];
__device__ float g_nll[MROWS];

// ======================= TF32 mma.sync helpers (sm_80+ portable) ============
__device__ __forceinline__ uint32_t f2tf32(float f) {
    uint32_t r;
    asm("cvt.rna.tf32.f32 %0, %1;" : "=r"(r) : "f"(f));
    return r;
}

__device__ __forceinline__ void mma_tf32(float* c, const uint32_t* a, const uint32_t* b) {
    asm volatile(
        "mma.sync.aligned.m16n8k8.row.col.f32.tf32.tf32.f32 "
        "{%0,%1,%2,%3}, {%4,%5,%6,%7}, {%8,%9}, {%0,%1,%2,%3};"
        : "+f"(c[0]), "+f"(c[1]), "+f"(c[2]), "+f"(c[3])
        : "r"(a[0]), "r"(a[1]), "r"(a[2]), "r"(a[3]),
          "r"(b[0]), "r"(b[1]));
}

// ============ TF32 tensor GEMM: C[M,N] = A[M,K] @ B^T  (B stored [N,K]) =====
// CTA tile 128x128x32, 256 threads = 8 warps (2m x 4n), warp tile 64x32.
// Requires M%128==0, N%128==0, K%32==0. A,B row strides lda/ldb, 16B aligned.
#define TBM 128
#define TBN 128
#define TBK 32
#define SPAD 36   // smem row stride in floats: bank = (4g+tg)%32, conflict-free

__global__ void __launch_bounds__(256, 2)
gemm_mma(const float* __restrict__ A, const float* __restrict__ B,
         const float* __restrict__ bias, float* __restrict__ C,
         int K, int lda, int ldb, int ldc, int relu)
{
    __shared__ float As[TBM][SPAD];
    __shared__ float Bs[TBN][SPAD];

    const int tid  = threadIdx.x;
    const int wid  = tid >> 5;
    const int lane = tid & 31;
    const int g    = lane >> 2;       // group 0..7
    const int tg   = lane & 3;        // thread-in-group 0..3
    const int wm   = wid >> 2;        // 0..1
    const int wn   = wid & 3;         // 0..3

    const int bm = blockIdx.y * TBM;
    const int bn = blockIdx.x * TBN;

    // global->smem mapping: each thread owns one row-half (16 floats = 4 float4)
    const int r = tid >> 1;           // 0..127
    const int h = (tid & 1) * 16;     // 0 or 16

    const float* ga = A + (size_t)(bm + r) * lda + h;
    const float* gb = B + (size_t)(bn + r) * ldb + h;

    float acc[4][4][4];
    #pragma unroll
    for (int i = 0; i < 4; i++)
        #pragma unroll
        for (int j = 0; j < 4; j++)
            #pragma unroll
            for (int e = 0; e < 4; e++) acc[i][j][e] = 0.f;

    const int KT = K / TBK;
    float4 ra[4], rb[4];

    // prologue: tile 0
    #pragma unroll
    for (int c = 0; c < 4; c++) {
        ra[c] = *(const float4*)(ga + 4 * c);
        rb[c] = *(const float4*)(gb + 4 * c);
    }
    #pragma unroll
    for (int c = 0; c < 4; c++) {
        *(float4*)&As[r][h + 4 * c] = ra[c];
        *(float4*)&Bs[r][h + 4 * c] = rb[c];
    }
    __syncthreads();

    for (int kt = 0; kt < KT; kt++) {
        // issue next tile's global loads early
        if (kt + 1 < KT) {
            const float* pa = ga + (size_t)(kt + 1) * TBK;
            const float* pb = gb + (size_t)(kt + 1) * TBK;
            #pragma unroll
            for (int c = 0; c < 4; c++) {
                ra[c] = *(const float4*)(pa + 4 * c);
                rb[c] = *(const float4*)(pb + 4 * c);
            }
        }

        // compute: 4 k-steps of m16n8k8
        #pragma unroll
        for (int ks = 0; ks < 4; ks++) {
            const int k0 = ks * 8;
            uint32_t af[4][4], bf[4][2];
            #pragma unroll
            for (int i = 0; i < 4; i++) {
                const int m0 = wm * 64 + i * 16;
                af[i][0] = f2tf32(As[m0 + g    ][k0 + tg    ]);
                af[i][1] = f2tf32(As[m0 + g + 8][k0 + tg    ]);
                af[i][2] = f2tf32(As[m0 + g    ][k0 + tg + 4]);
                af[i][3] = f2tf32(As[m0 + g + 8][k0 + tg + 4]);
            }
            #pragma unroll
            for (int j = 0; j < 4; j++) {
                const int n0 = wn * 32 + j * 8;
                bf[j][0] = f2tf32(Bs[n0 + g][k0 + tg    ]);
                bf[j][1] = f2tf32(Bs[n0 + g][k0 + tg + 4]);
            }
            #pragma unroll
            for (int i = 0; i < 4; i++)
                #pragma unroll
                for (int j = 0; j < 4; j++)
                    mma_tf32(acc[i][j], af[i], bf[j]);
        }

        __syncthreads();
        if (kt + 1 < KT) {
            #pragma unroll
            for (int c = 0; c < 4; c++) {
                *(float4*)&As[r][h + 4 * c] = ra[c];
                *(float4*)&Bs[r][h + 4 * c] = rb[c];
            }
            __syncthreads();
        }
    }

    // epilogue: acc[i][j]: c0 @(m0+g, n0+tg*2), c1 +1 col, c2/c3 @ m0+g+8
    #pragma unroll
    for (int i = 0; i < 4; i++) {
        const int m0 = bm + wm * 64 + i * 16 + g;
        #pragma unroll
        for (int j = 0; j < 4; j++) {
            const int n0 = bn + wn * 32 + j * 8 + tg * 2;
            float2 v0 = make_float2(acc[i][j][0], acc[i][j][1]);
            float2 v1 = make_float2(acc[i][j][2], acc[i][j][3]);
            if (bias) {
                float2 bv = *(const float2*)(bias + n0);
                v0.x += bv.x; v0.y += bv.y;
                v1.x += bv.x; v1.y += bv.y;
            }
            if (relu) {
                v0.x = fmaxf(v0.x, 0.f); v0.y = fmaxf(v0.y, 0.f);
                v1.x = fmaxf(v1.x, 0.f); v1.y = fmaxf(v1.y, 0.f);
            }
            *(float2*)(C + (size_t)m0 * ldc + n0)       = v0;
            *(float2*)(C + (size_t)(m0 + 8) * ldc + n0) = v1;
        }
    }
}

// ---------------- tiled transpose: out[z][c][r] = in[z][r][c] ----------------
__global__ __launch_bounds__(256)
void transpose_kernel(const float* __restrict__ in, float* __restrict__ out,
                      int R, int C) {
    __shared__ float t[32][33];
    long long z = blockIdx.z;
    in  += z * (long long)R * C;
    out += z * (long long)R * C;
    int c0 = blockIdx.x * 32, r0 = blockIdx.y * 32;
    int tx = threadIdx.x & 31, ty = threadIdx.x >> 5;   // 32 x 8
    #pragma unroll
    for (int i = 0; i < 4; i++)
        t[ty + i * 8][tx] = in[(long long)(r0 + ty + i * 8) * C + c0 + tx];
    __syncthreads();
    #pragma unroll
    for (int i = 0; i < 4; i++)
        out[(long long)(c0 + ty + i * 8) * R + r0 + tx] = t[tx][ty + i * 8];
}

// ---------------- embedding: x = tok_emb[index] + pos_emb[:T] ---------------
__global__ void embed_kernel(const int* __restrict__ index,
                             const float* __restrict__ tok,
                             const float* __restrict__ pos) {
    int i = blockIdx.x * blockDim.x + threadIdx.x;
    if (i >= MROWS * DIM) return;
    int d = i % DIM;
    int bt = i / DIM;
    int t = bt % SEQ;
    g_x[i] = tok[(long long)index[bt] * DIM + d] + pos[(long long)t * DIM + d];
}

// ---------------- generic batched SGEMM (fp32 path for attention/LM) --------
#define BM 64
#define BN 64
#define BKK 16

__global__ __launch_bounds__(256)
void gemm_kernel(const float* __restrict__ A, const float* __restrict__ Bm,
                 const float* __restrict__ bias, float* __restrict__ C,
                 int M, int N, int K, int lda, int ldb, int ldc, int zdiv,
                 long long sA1, long long sA2,
                 long long sB1, long long sB2,
                 long long sC1, long long sC2, int relu)
{
    int z = blockIdx.z;
    int z1 = z / zdiv, z2 = z % zdiv;
    A  += z1 * sA1 + z2 * sA2;
    Bm += z1 * sB1 + z2 * sB2;
    C  += z1 * sC1 + z2 * sC2;

    int bm = blockIdx.y * BM;
    int bn = blockIdx.x * BN;
    __shared__ float As[BKK][BM + 1];
    __shared__ float Bs[BKK][BN + 1];

    int tid = threadIdx.x;
    int tx = tid & 15, ty = tid >> 4;
    float acc[4][4] = {};

    for (int k0 = 0; k0 < K; k0 += BKK) {
        #pragma unroll
        for (int i = 0; i < 4; i++) {
            int idx = tid + i * 256;
            int m  = idx >> 4;
            int kk = idx & 15;
            int gm = bm + m;
            float v = 0.f;
            if (gm < M) v = A[(long long)gm * lda + (k0 + kk)];
            As[kk][m] = v;
        }
        #pragma unroll
        for (int i = 0; i < 4; i++) {
            int idx = tid + i * 256;
            int kk = idx >> 6;
            int n  = idx & 63;
            int gn = bn + n;
            float v = 0.f;
            if (gn < N) v = Bm[(long long)(k0 + kk) * ldb + gn];
            Bs[kk][n] = v;
        }
        __syncthreads();
        #pragma unroll
        for (int kk = 0; kk < BKK; kk++) {
            float a[4], b[4];
            #pragma unroll
            for (int i = 0; i < 4; i++) a[i] = As[kk][ty * 4 + i];
            #pragma unroll
            for (int j = 0; j < 4; j++) b[j] = Bs[kk][tx * 4 + j];
            #pragma unroll
            for (int i = 0; i < 4; i++)
                #pragma unroll
                for (int j = 0; j < 4; j++)
                    acc[i][j] += a[i] * b[j];
        }
        __syncthreads();
    }

    #pragma unroll
    for (int i = 0; i < 4; i++) {
        int gm = bm + ty * 4 + i;
        if (gm >= M) continue;
        #pragma unroll
        for (int j = 0; j < 4; j++) {
            int gn = bn + tx * 4 + j;
            if (gn >= N) continue;
            float v = acc[i][j];
            if (bias) v += bias[gn];
            if (relu) v = fmaxf(v, 0.f);
            C[(long long)gm * ldc + gn] = v;
        }
    }
}

// ---------------- causal scores: wei = scale * Q @ K^T, mask -1e9 -----------
__global__ __launch_bounds__(256)
void scores_kernel() {
    int z = blockIdx.z;                    // b*NH + h
    int b = z / NH, h = z % NH;
    const float* Q  = g_q + (long long)b * SEQ * DIM + h * HSZ;
    const float* Kp = g_k + (long long)b * SEQ * DIM + h * HSZ;
    float* C = g_wei + (long long)z * SEQ * SEQ;

    int t0 = blockIdx.y * 64;
    int s0 = blockIdx.x * 64;
    int tid = threadIdx.x;
    int tx = tid & 15, ty = tid >> 4;

    if (s0 > t0 + 63) {
        #pragma unroll
        for (int i = 0; i < 4; i++)
            #pragma unroll
            for (int j = 0; j < 4; j++)
                C[(long long)(t0 + ty * 4 + i) * SEQ + (s0 + tx * 4 + j)] = -1e9f;
        return;
    }

    __shared__ float Qs[16][65];
    __shared__ float Ks[16][65];
    float acc[4][4] = {};

    for (int k0 = 0; k0 < HSZ; k0 += 16) {
        #pragma unroll
        for (int i = 0; i < 4; i++) {
            int idx = tid + i * 256;
            int m  = idx >> 4;
            int kk = idx & 15;
            Qs[kk][m] = Q[(long long)(t0 + m) * DIM + (k0 + kk)];
            Ks[kk][m] = Kp[(long long)(s0 + m) * DIM + (k0 + kk)];
        }
        __syncthreads();
        #pragma unroll
        for (int kk = 0; kk < 16; kk++) {
            float a[4], bb[4];
            #pragma unroll
            for (int i = 0; i < 4; i++) a[i] = Qs[kk][ty * 4 + i];
            #pragma unroll
            for (int j = 0; j < 4; j++) bb[j] = Ks[kk][tx * 4 + j];
            #pragma unroll
            for (int i = 0; i < 4; i++)
                #pragma unroll
                for (int j = 0; j < 4; j++)
                    acc[i][j] += a[i] * bb[j];
        }
        __syncthreads();
    }

    const float scale = 0.125f;
    #pragma unroll
    for (int i = 0; i < 4; i++) {
        int t = t0 + ty * 4 + i;
        #pragma unroll
        for (int j = 0; j < 4; j++) {
            int s = s0 + tx * 4 + j;
            C[(long long)t * SEQ + s] = (s <= t) ? acc[i][j] * scale : -1e9f;
        }
    }
}

// ---------------- row softmax over T=1024 -----------------------------------
__global__ __launch_bounds__(256)
void softmax_kernel() {
    long long row = blockIdx.x;
    float* p = g_wei + row * SEQ;
    __shared__ float red[256];
    int tid = threadIdx.x;

    float v[4];
    float m = -1e30f;
    #pragma unroll
    for (int i = 0; i < 4; i++) { v[i] = p[tid + i * 256]; m = fmaxf(m, v[i]); }
    red[tid] = m; __syncthreads();
    for (int s = 128; s > 0; s >>= 1) {
        if (tid < s) red[tid] = fmaxf(red[tid], red[tid + s]);
        __syncthreads();
    }
    m = red[0]; __syncthreads();

    float sum = 0.f;
    #pragma unroll
    for (int i = 0; i < 4; i++) { v[i] = expf(v[i] - m); sum += v[i]; }
    red[tid] = sum; __syncthreads();
    for (int s = 128; s > 0; s >>= 1) {
        if (tid < s) red[tid] += red[tid + s];
        __syncthreads();
    }
    float inv = 1.f / red[0];
    #pragma unroll
    for (int i = 0; i < 4; i++) p[tid + i * 256] = v[i] * inv;
}

// ---------------- x = LayerNorm(x (+ y)) * g + b ----------------------------
__global__ __launch_bounds__(256)
void add_ln_kernel(float* __restrict__ x, const float* __restrict__ y,
                   const float* __restrict__ g, const float* __restrict__ bb) {
    int row = blockIdx.x;
    float* xr = x + (long long)row * DIM;
    const float* yr = y ? y + (long long)row * DIM : nullptr;
    __shared__ float s[DIM];
    __shared__ float red[256];
    int tid = threadIdx.x;

    float local = 0.f;
    #pragma unroll
    for (int i = 0; i < 4; i++) {
        int d = tid + i * 256;
        float v = xr[d];
        if (yr) v += yr[d];
        s[d] = v;
        local += v;
    }
    red[tid] = local; __syncthreads();
    for (int st = 128; st > 0; st >>= 1) {
        if (tid < st) red[tid] += red[tid + st];
        __syncthreads();
    }
    float mean = red[0] * (1.0f / DIM); __syncthreads();

    local = 0.f;
    #pragma unroll
    for (int i = 0; i < 4; i++) {
        float d2 = s[tid + i * 256] - mean;
        local += d2 * d2;
    }
    red[tid] = local; __syncthreads();
    for (int st = 128; st > 0; st >>= 1) {
        if (tid < st) red[tid] += red[tid + st];
        __syncthreads();
    }
    float inv = rsqrtf(red[0] * (1.0f / DIM) + 1e-5f);
    #pragma unroll
    for (int i = 0; i < 4; i++) {
        int d = tid + i * 256;
        xr[d] = (s[d] - mean) * inv * g[d] + bb[d];
    }
}

// ---------------- per-row NLL from logits (V=96) -----------------------------
__global__ __launch_bounds__(128)
void nll_kernel(const float* __restrict__ logits, const int* __restrict__ targets) {
    int row = blockIdx.x;
    const float* p = logits + (long long)row * VOCABN;
    __shared__ float red[128];
    int tid = threadIdx.x;

    float v = (tid < VOCABN) ? p[tid] : -1e30f;
    red[tid] = v; __syncthreads();
    for (int s = 64; s > 0; s >>= 1) {
        if (tid < s) red[tid] = fmaxf(red[tid], red[tid + s]);
        __syncthreads();
    }
    float m = red[0]; __syncthreads();

    float e = (tid < VOCABN) ? expf(v - m) : 0.f;
    red[tid] = e; __syncthreads();
    for (int s = 64; s > 0; s >>= 1) {
        if (tid < s) red[tid] += red[tid + s];
        __syncthreads();
    }
    if (tid == 0) {
        float lse = m + logf(red[0]);
        g_nll[row] = lse - p[targets[row]];
    }
}

__global__ __launch_bounds__(256)
void loss_kernel(float* __restrict__ out) {
    __shared__ float red[256];
    int tid = threadIdx.x;
    float s = 0.f;
    for (int i = tid; i < MROWS; i += 256) s += g_nll[i];
    red[tid] = s; __syncthreads();
    for (int st = 128; st > 0; st >>= 1) {
        if (tid < st) red[tid] += red[tid + st];
        __syncthreads();
    }
    if (tid == 0) out[0] = red[0] * (1.0f / MROWS);
}

// ---------------- host-side launch helpers ----------------------------------
static float* sym(const void* s) {
    void* p = nullptr;
    cudaGetSymbolAddress(&p, s);
    return (float*)p;
}

static void run_gemm(const float* A, const float* B, const float* bias, float* C,
                     int M, int N, int K, int lda, int ldb, int ldc,
                     int gz, int zdiv,
                     long long sA1, long long sA2,
                     long long sB1, long long sB2,
                     long long sC1, long long sC2, int relu) {
    dim3 grid((N + BN - 1) / BN, (M + BM - 1) / BM, gz);
    gemm_kernel<<<grid, 256>>>(A, B, bias, C, M, N, K, lda, ldb, ldc, zdiv,
                               sA1, sA2, sB1, sB2, sC1, sC2, relu);
}

// TF32 tensor GEMM: C[M,N] = A[M,K] @ Bt^T  where Bt is [N,K] row-major
static void run_gemm_tc(const float* A, const float* Bt, const float* bias,
                        float* C, int M, int N, int K, int lda, int ldb, int ldc,
                        int relu) {
    dim3 grid(N / TBN, M / TBM);
    gemm_mma<<<grid, 256>>>(A, Bt, bias, C, K, lda, ldb, ldc, relu);
}

extern "C" void kernel_launch(void* const* d_in, const int* in_sizes, int n_in,
                              void* d_out, int out_size) {
    const int*   index   = (const int*)  d_in[0];
    const int*   targets = (const int*)  d_in[1];
    const float* tok     = (const float*)d_in[2];
    const float* pos     = (const float*)d_in[3];
    const float* Wq      = (const float*)d_in[4];
    const float* Wk      = (const float*)d_in[5];
    const float* Wv      = (const float*)d_in[6];
    const float* Wo      = (const float*)d_in[7];
    const float* bo      = (const float*)d_in[8];
    const float* W1      = (const float*)d_in[9];
    const float* b1      = (const float*)d_in[10];
    const float* W2      = (const float*)d_in[11];
    const float* b2      = (const float*)d_in[12];
    const float* ln1g    = (const float*)d_in[13];
    const float* ln1b    = (const float*)d_in[14];
    const float* ln2g    = (const float*)d_in[15];
    const float* ln2b    = (const float*)d_in[16];
    const float* lnfg    = (const float*)d_in[17];
    const float* lnfb    = (const float*)d_in[18];
    const float* Wlm     = (const float*)d_in[19];
    const float* blm     = (const float*)d_in[20];
    float* out = (float*)d_out;

    float* x   = sym(g_x);
    float* q   = sym(g_q);
    float* k   = sym(g_k);
    float* v   = sym(g_v);
    float* o   = sym(g_o);
    float* y   = sym(g_y);
    float* hb  = sym(g_h);
    float* wqT = sym(g_wqT);
    float* wkT = sym(g_wkT);
    float* wvT = sym(g_wvT);
    float* woT = sym(g_woT);
    float* w1T = sym(g_w1T);
    float* w2T = sym(g_w2T);

    // ---- weight transposes: W[K,N] -> Wt[N,K] (K-contiguous for mma B) -----
    {
        dim3 g1(HSZ / 32, DIM / 32, NL * NH);
        transpose_kernel<<<g1, 256>>>(Wq, wqT, DIM, HSZ);
        transpose_kernel<<<g1, 256>>>(Wk, wkT, DIM, HSZ);
        transpose_kernel<<<g1, 256>>>(Wv, wvT, DIM, HSZ);
        dim3 g2(DIM / 32, DIM / 32, NL);
        transpose_kernel<<<g2, 256>>>(Wo, woT, DIM, DIM);
        dim3 g3(FFD / 32, DIM / 32, NL);
        transpose_kernel<<<g3, 256>>>(W1, w1T, DIM, FFD);
        dim3 g4(DIM / 32, FFD / 32, NL);
        transpose_kernel<<<g4, 256>>>(W2, w2T, FFD, DIM);
    }

    // embedding
    {
        int n = MROWS * DIM;
        embed_kernel<<<(n + 255) / 256, 256>>>(index, tok, pos);
    }

    for (int l = 0; l < NL; l++) {
        const float* wqT_l = wqT + (long long)l * DIM * DIM;
        const float* wkT_l = wkT + (long long)l * DIM * DIM;
        const float* wvT_l = wvT + (long long)l * DIM * DIM;
        const float* woT_l = woT + (long long)l * DIM * DIM;
        const float* bo_l  = bo  + (long long)l * DIM;
        const float* w1T_l = w1T + (long long)l * DIM * FFD;
        const float* b1_l  = b1  + (long long)l * FFD;
        const float* w2T_l = w2T + (long long)l * FFD * DIM;
        const float* b2_l  = b2  + (long long)l * DIM;

        // q/k/v projections via tensor cores
        run_gemm_tc(x, wqT_l, nullptr, q, MROWS, DIM, DIM, DIM, DIM, DIM, 0);
        run_gemm_tc(x, wkT_l, nullptr, k, MROWS, DIM, DIM, DIM, DIM, DIM, 0);
        run_gemm_tc(x, wvT_l, nullptr, v, MROWS, DIM, DIM, DIM, DIM, DIM, 0);

        // causal attention scores + softmax (fp32 path)
        {
            dim3 grid(SEQ / 64, SEQ / 64, BATCH * NH);
            scores_kernel<<<grid, 256>>>();
        }
        softmax_kernel<<<BATCH * NH * SEQ, 256>>>();

        // attention output: per (b,h)  O_bh = P_bh @ V_bh (fp32 path)
        run_gemm(sym(g_wei), v, nullptr, o,
                 SEQ, HSZ, SEQ, SEQ, DIM, DIM,
                 BATCH * NH, NH,
                 (long long)NH * SEQ * SEQ, (long long)SEQ * SEQ,
                 (long long)SEQ * DIM,      (long long)HSZ,
                 (long long)SEQ * DIM,      (long long)HSZ,
                 0);

        // output projection + residual LN
        run_gemm_tc(o, woT_l, bo_l, y, MROWS, DIM, DIM, DIM, DIM, DIM, 0);
        add_ln_kernel<<<MROWS, 256>>>(x, y, ln1g + (long long)l * DIM,
                                            ln1b + (long long)l * DIM);

        // feed-forward + residual LN
        run_gemm_tc(x, w1T_l, b1_l, hb, MROWS, FFD, DIM, DIM, DIM, FFD, 1);
        run_gemm_tc(hb, w2T_l, b2_l, y, MROWS, DIM, FFD, FFD, FFD, DIM, 0);
        add_ln_kernel<<<MROWS, 256>>>(x, y, ln2g + (long long)l * DIM,
                                            ln2b + (long long)l * DIM);
    }

    // final LN (no residual)
    add_ln_kernel<<<MROWS, 256>>>(x, nullptr, lnfg, lnfb);

    // logits = xf @ Wlm + blm (N=96: fp32 path, negligible flops)
    run_gemm(x, Wlm, blm, out, MROWS, VOCABN, DIM, DIM, VOCABN, VOCABN,
             1, 1, 0, 0, 0, 0, 0, 0, 0);

    // loss
    nll_kernel<<<MROWS, 128>>>(out, targets);
    if (out_size > MROWS * VOCABN) {
        loss_kernel<<<1, 256>>>(out + (long long)MROWS * VOCABN);
    }
}

// round 4
// speedup vs baseline: 3.1544x; 1.2825x over previous
#include <cuda_runtime.h>
#include <math.h>
#include <stdint.h>

#define VOCABN 96
#define DIM 1024
#define NH 16
#define HSZ 64
#define NL 8
#define BATCH 8
#define SEQ 1024
#define FFD 4096
#define MROWS (BATCH*SEQ)   // 8192

// ---------------- scratch (device globals; no allocations allowed) ----------
__device__ float g_x[MROWS*DIM];
__device__ float g_q[MROWS*DIM];
__device__ float g_k[MROWS*DIM];
__device__ float g_v[MROWS*DIM];
__device__ float g_o[MROWS*DIM];
__device__ float g_y[MROWS*DIM];
__device__ float g_h[(long long)MROWS*FFD];
__device__ float g_wqT[NL*DIM*DIM];
__device__ float g_wkT[NL*DIM*DIM];
__device__ float g_wvT[NL*DIM*DIM];
__device__ float g_woT[NL*DIM*DIM];
__device__ float g_w1T[(long long)NL*DIM*FFD];
__device__ float g_w2T[(long long)NL*FFD*DIM];
__device__ float g_nll[MROWS];

// ======================= TF32 mma.sync helpers (sm_80+ portable) ============
__device__ __forceinline__ uint32_t f2tf32(float f) {
    uint32_t r;
    asm("cvt.rna.tf32.f32 %0, %1;" : "=r"(r) : "f"(f));
    return r;
}

__device__ __forceinline__ float f2tf32f(float f) {
    return __uint_as_float(f2tf32(f));
}

__device__ __forceinline__ void mma_tf32(float* c, const uint32_t* a, const uint32_t* b) {
    asm volatile(
        "mma.sync.aligned.m16n8k8.row.col.f32.tf32.tf32.f32 "
        "{%0,%1,%2,%3}, {%4,%5,%6,%7}, {%8,%9}, {%0,%1,%2,%3};"
        : "+f"(c[0]), "+f"(c[1]), "+f"(c[2]), "+f"(c[3])
        : "r"(a[0]), "r"(a[1]), "r"(a[2]), "r"(a[3]),
          "r"(b[0]), "r"(b[1]));
}

// ============ TF32 tensor GEMM: C[M,N] = A[M,K] @ B^T  (B stored [N,K]) =====
// CTA tile 128x128x32, 256 threads = 8 warps (2m x 4n), warp tile 64x32.
#define TBM 128
#define TBN 128
#define TBK 32
#define SPAD 36   // smem row stride: bank = (4g+tg)%32, conflict-free frag loads

__global__ void __launch_bounds__(256, 2)
gemm_mma(const float* __restrict__ A, const float* __restrict__ B,
         const float* __restrict__ bias, float* __restrict__ C,
         int K, int lda, int ldb, int ldc, int relu)
{
    __shared__ float As[TBM][SPAD];
    __shared__ float Bs[TBN][SPAD];

    const int tid  = threadIdx.x;
    const int wid  = tid >> 5;
    const int lane = tid & 31;
    const int g    = lane >> 2;
    const int tg   = lane & 3;
    const int wm   = wid >> 2;
    const int wn   = wid & 3;

    const int bm = blockIdx.y * TBM;
    const int bn = blockIdx.x * TBN;

    const int r = tid >> 1;
    const int h = (tid & 1) * 16;

    const float* ga = A + (size_t)(bm + r) * lda + h;
    const float* gb = B + (size_t)(bn + r) * ldb + h;

    float acc[4][4][4];
    #pragma unroll
    for (int i = 0; i < 4; i++)
        #pragma unroll
        for (int j = 0; j < 4; j++)
            #pragma unroll
            for (int e = 0; e < 4; e++) acc[i][j][e] = 0.f;

    const int KT = K / TBK;
    float4 ra[4], rb[4];

    // prologue: tile 0 (convert to tf32 once, on the smem-store path)
    #pragma unroll
    for (int c = 0; c < 4; c++) {
        ra[c] = *(const float4*)(ga + 4 * c);
        rb[c] = *(const float4*)(gb + 4 * c);
    }
    #pragma unroll
    for (int c = 0; c < 4; c++) {
        float4 ta = make_float4(f2tf32f(ra[c].x), f2tf32f(ra[c].y),
                                f2tf32f(ra[c].z), f2tf32f(ra[c].w));
        float4 tb = make_float4(f2tf32f(rb[c].x), f2tf32f(rb[c].y),
                                f2tf32f(rb[c].z), f2tf32f(rb[c].w));
        *(float4*)&As[r][h + 4 * c] = ta;
        *(float4*)&Bs[r][h + 4 * c] = tb;
    }
    __syncthreads();

    for (int kt = 0; kt < KT; kt++) {
        if (kt + 1 < KT) {
            const float* pa = ga + (size_t)(kt + 1) * TBK;
            const float* pb = gb + (size_t)(kt + 1) * TBK;
            #pragma unroll
            for (int c = 0; c < 4; c++) {
                ra[c] = *(const float4*)(pa + 4 * c);
                rb[c] = *(const float4*)(pb + 4 * c);
            }
        }

        #pragma unroll
        for (int ks = 0; ks < 4; ks++) {
            const int k0 = ks * 8;
            uint32_t af[4][4], bf[4][2];
            #pragma unroll
            for (int i = 0; i < 4; i++) {
                const int m0 = wm * 64 + i * 16;
                af[i][0] = __float_as_uint(As[m0 + g    ][k0 + tg    ]);
                af[i][1] = __float_as_uint(As[m0 + g + 8][k0 + tg    ]);
                af[i][2] = __float_as_uint(As[m0 + g    ][k0 + tg + 4]);
                af[i][3] = __float_as_uint(As[m0 + g + 8][k0 + tg + 4]);
            }
            #pragma unroll
            for (int j = 0; j < 4; j++) {
                const int n0 = wn * 32 + j * 8;
                bf[j][0] = __float_as_uint(Bs[n0 + g][k0 + tg    ]);
                bf[j][1] = __float_as_uint(Bs[n0 + g][k0 + tg + 4]);
            }
            #pragma unroll
            for (int i = 0; i < 4; i++)
                #pragma unroll
                for (int j = 0; j < 4; j++)
                    mma_tf32(acc[i][j], af[i], bf[j]);
        }

        __syncthreads();
        if (kt + 1 < KT) {
            #pragma unroll
            for (int c = 0; c < 4; c++) {
                float4 ta = make_float4(f2tf32f(ra[c].x), f2tf32f(ra[c].y),
                                        f2tf32f(ra[c].z), f2tf32f(ra[c].w));
                float4 tb = make_float4(f2tf32f(rb[c].x), f2tf32f(rb[c].y),
                                        f2tf32f(rb[c].z), f2tf32f(rb[c].w));
                *(float4*)&As[r][h + 4 * c] = ta;
                *(float4*)&Bs[r][h + 4 * c] = tb;
            }
            __syncthreads();
        }
    }

    #pragma unroll
    for (int i = 0; i < 4; i++) {
        const int m0 = bm + wm * 64 + i * 16 + g;
        #pragma unroll
        for (int j = 0; j < 4; j++) {
            const int n0 = bn + wn * 32 + j * 8 + tg * 2;
            float2 v0 = make_float2(acc[i][j][0], acc[i][j][1]);
            float2 v1 = make_float2(acc[i][j][2], acc[i][j][3]);
            if (bias) {
                float2 bv = *(const float2*)(bias + n0);
                v0.x += bv.x; v0.y += bv.y;
                v1.x += bv.x; v1.y += bv.y;
            }
            if (relu) {
                v0.x = fmaxf(v0.x, 0.f); v0.y = fmaxf(v0.y, 0.f);
                v1.x = fmaxf(v1.x, 0.f); v1.y = fmaxf(v1.y, 0.f);
            }
            *(float2*)(C + (size_t)m0 * ldc + n0)       = v0;
            *(float2*)(C + (size_t)(m0 + 8) * ldc + n0) = v1;
        }
    }
}

// ============ Flash attention (causal, online softmax, TF32 mma) ============
// grid = (16 q-tiles, B*NH). block = 128 threads (4 warps, 16 q-rows each).
// Q tile 64 rows, K/V tiles 64 rows. All operands tf32 in smem, fp32 accum.
#define FPAD 68
#define FA_SMEM ((3*64*FPAD + 4*16*FPAD) * 4)   // 69632 bytes

__global__ void __launch_bounds__(128, 2)
flash_kernel()
{
    extern __shared__ float sm[];
    float* Qs = sm;                  // [64][FPAD]
    float* Ks = sm + 64 * FPAD;      // [64][FPAD]
    float* Vs = sm + 2 * 64 * FPAD;  // [64][FPAD]
    float* Ps = sm + 3 * 64 * FPAD;  // [4][16][FPAD]

    const int bh = blockIdx.y;
    const int b = bh >> 4, hh = bh & 15;
    const int qt = gridDim.x - 1 - blockIdx.x;   // heavy blocks first
    const int tid = threadIdx.x;
    const int wid = tid >> 5, lane = tid & 31;
    const int g = lane >> 2, tg = lane & 3;

    const float* Qg = g_q + ((size_t)b * SEQ + qt * 64) * DIM + hh * HSZ;
    const float* Kg = g_k + (size_t)b * SEQ * DIM + hh * HSZ;
    const float* Vg = g_v + (size_t)b * SEQ * DIM + hh * HSZ;

    // load Q tile -> tf32 smem
    {
        const int r = tid >> 1, c0 = (tid & 1) * 32;
        const float* src = Qg + (size_t)r * DIM + c0;
        float* dst = Qs + r * FPAD + c0;
        #pragma unroll
        for (int c = 0; c < 32; c += 4) {
            float4 v = *(const float4*)(src + c);
            dst[c + 0] = f2tf32f(v.x);
            dst[c + 1] = f2tf32f(v.y);
            dst[c + 2] = f2tf32f(v.z);
            dst[c + 3] = f2tf32f(v.w);
        }
    }

    float m0 = -1e30f, m1 = -1e30f, l0 = 0.f, l1 = 0.f;
    float oacc[8][4];
    #pragma unroll
    for (int nb = 0; nb < 8; nb++)
        #pragma unroll
        for (int e = 0; e < 4; e++) oacc[nb][e] = 0.f;

    float* Pw = Ps + wid * 16 * FPAD;
    const float* qb = Qs + (wid * 16) * FPAD;
    const int row0 = qt * 64 + wid * 16 + g;      // global q row (thread's row g)

    for (int kt = 0; kt <= qt; kt++) {
        __syncthreads();   // prev iteration's PV reads of Ks/Vs done
        // load K,V tiles -> tf32 smem
        {
            const int r = tid >> 1, c0 = (tid & 1) * 32;
            const float* ksrc = Kg + ((size_t)(kt * 64 + r)) * DIM + c0;
            const float* vsrc = Vg + ((size_t)(kt * 64 + r)) * DIM + c0;
            float* kdst = Ks + r * FPAD + c0;
            float* vdst = Vs + r * FPAD + c0;
            #pragma unroll
            for (int c = 0; c < 32; c += 4) {
                float4 kv = *(const float4*)(ksrc + c);
                float4 vv = *(const float4*)(vsrc + c);
                kdst[c + 0] = f2tf32f(kv.x);
                kdst[c + 1] = f2tf32f(kv.y);
                kdst[c + 2] = f2tf32f(kv.z);
                kdst[c + 3] = f2tf32f(kv.w);
                vdst[c + 0] = f2tf32f(vv.x);
                vdst[c + 1] = f2tf32f(vv.y);
                vdst[c + 2] = f2tf32f(vv.z);
                vdst[c + 3] = f2tf32f(vv.w);
            }
        }
        __syncthreads();

        // S = Q @ K^T for this warp's 16 rows x 64 kv cols
        float sacc[8][4];
        #pragma unroll
        for (int nb = 0; nb < 8; nb++)
            #pragma unroll
            for (int e = 0; e < 4; e++) sacc[nb][e] = 0.f;

        #pragma unroll
        for (int ks = 0; ks < 8; ks++) {
            const int k0 = ks * 8;
            uint32_t af[4];
            af[0] = __float_as_uint(qb[(g    ) * FPAD + k0 + tg    ]);
            af[1] = __float_as_uint(qb[(g + 8) * FPAD + k0 + tg    ]);
            af[2] = __float_as_uint(qb[(g    ) * FPAD + k0 + tg + 4]);
            af[3] = __float_as_uint(qb[(g + 8) * FPAD + k0 + tg + 4]);
            #pragma unroll
            for (int nb = 0; nb < 8; nb++) {
                uint32_t bf[2];
                bf[0] = __float_as_uint(Ks[(nb * 8 + g) * FPAD + k0 + tg    ]);
                bf[1] = __float_as_uint(Ks[(nb * 8 + g) * FPAD + k0 + tg + 4]);
                mma_tf32(sacc[nb], af, bf);
            }
        }

        // scale + causal mask (diagonal tile only)
        const float scale = 0.125f;
        #pragma unroll
        for (int nb = 0; nb < 8; nb++)
            #pragma unroll
            for (int e = 0; e < 4; e++) sacc[nb][e] *= scale;
        if (kt == qt) {
            #pragma unroll
            for (int nb = 0; nb < 8; nb++) {
                const int col = kt * 64 + nb * 8 + tg * 2;
                if (col     > row0) sacc[nb][0] = -1e9f;
                if (col + 1 > row0) sacc[nb][1] = -1e9f;
                if (col     > row0 + 8) sacc[nb][2] = -1e9f;
                if (col + 1 > row0 + 8) sacc[nb][3] = -1e9f;
            }
        }

        // tile row max (rows g and g+8), reduce across quad lanes
        float tmax0 = -1e30f, tmax1 = -1e30f;
        #pragma unroll
        for (int nb = 0; nb < 8; nb++) {
            tmax0 = fmaxf(tmax0, fmaxf(sacc[nb][0], sacc[nb][1]));
            tmax1 = fmaxf(tmax1, fmaxf(sacc[nb][2], sacc[nb][3]));
        }
        tmax0 = fmaxf(tmax0, __shfl_xor_sync(0xffffffff, tmax0, 1));
        tmax0 = fmaxf(tmax0, __shfl_xor_sync(0xffffffff, tmax0, 2));
        tmax1 = fmaxf(tmax1, __shfl_xor_sync(0xffffffff, tmax1, 1));
        tmax1 = fmaxf(tmax1, __shfl_xor_sync(0xffffffff, tmax1, 2));

        const float mn0 = fmaxf(m0, tmax0);
        const float mn1 = fmaxf(m1, tmax1);
        const float a0 = __expf(m0 - mn0);
        const float a1 = __expf(m1 - mn1);
        m0 = mn0; m1 = mn1;

        // P = exp(S - m), accumulate row sums, stage P (tf32) in smem
        float sum0 = 0.f, sum1 = 0.f;
        #pragma unroll
        for (int nb = 0; nb < 8; nb++) {
            float p00 = __expf(sacc[nb][0] - mn0);
            float p01 = __expf(sacc[nb][1] - mn0);
            float p10 = __expf(sacc[nb][2] - mn1);
            float p11 = __expf(sacc[nb][3] - mn1);
            sum0 += p00 + p01;
            sum1 += p10 + p11;
            float* p0 = Pw + g * FPAD + nb * 8 + tg * 2;
            float* p1 = Pw + (g + 8) * FPAD + nb * 8 + tg * 2;
            p0[0] = f2tf32f(p00); p0[1] = f2tf32f(p01);
            p1[0] = f2tf32f(p10); p1[1] = f2tf32f(p11);
        }
        sum0 += __shfl_xor_sync(0xffffffff, sum0, 1);
        sum0 += __shfl_xor_sync(0xffffffff, sum0, 2);
        sum1 += __shfl_xor_sync(0xffffffff, sum1, 1);
        sum1 += __shfl_xor_sync(0xffffffff, sum1, 2);
        l0 = l0 * a0 + sum0;
        l1 = l1 * a1 + sum1;

        // rescale running O
        #pragma unroll
        for (int nb = 0; nb < 8; nb++) {
            oacc[nb][0] *= a0; oacc[nb][1] *= a0;
            oacc[nb][2] *= a1; oacc[nb][3] *= a1;
        }

        __syncwarp();

        // O += P @ V   (k over 64 kv rows, n over 64 head dims)
        #pragma unroll
        for (int kb = 0; kb < 8; kb++) {
            const int k0 = kb * 8;
            uint32_t pf[4];
            pf[0] = __float_as_uint(Pw[(g    ) * FPAD + k0 + tg    ]);
            pf[1] = __float_as_uint(Pw[(g + 8) * FPAD + k0 + tg    ]);
            pf[2] = __float_as_uint(Pw[(g    ) * FPAD + k0 + tg + 4]);
            pf[3] = __float_as_uint(Pw[(g + 8) * FPAD + k0 + tg + 4]);
            #pragma unroll
            for (int nb = 0; nb < 8; nb++) {
                uint32_t vf[2];
                vf[0] = __float_as_uint(Vs[(k0 + tg    ) * FPAD + nb * 8 + g]);
                vf[1] = __float_as_uint(Vs[(k0 + tg + 4) * FPAD + nb * 8 + g]);
                mma_tf32(oacc[nb], pf, vf);
            }
        }
    }

    // normalize + write to g_o (concat-head layout)
    const float inv0 = 1.f / l0;
    const float inv1 = 1.f / l1;
    float* orow0 = g_o + ((size_t)b * SEQ + row0    ) * DIM + hh * HSZ;
    float* orow1 = g_o + ((size_t)b * SEQ + row0 + 8) * DIM + hh * HSZ;
    #pragma unroll
    for (int nb = 0; nb < 8; nb++) {
        const int c = nb * 8 + tg * 2;
        *(float2*)(orow0 + c) = make_float2(oacc[nb][0] * inv0, oacc[nb][1] * inv0);
        *(float2*)(orow1 + c) = make_float2(oacc[nb][2] * inv1, oacc[nb][3] * inv1);
    }
}

// ---------------- tiled transpose: out[z][c][r] = in[z][r][c] ----------------
__global__ __launch_bounds__(256)
void transpose_kernel(const float* __restrict__ in, float* __restrict__ out,
                      int R, int C) {
    __shared__ float t[32][33];
    long long z = blockIdx.z;
    in  += z * (long long)R * C;
    out += z * (long long)R * C;
    int c0 = blockIdx.x * 32, r0 = blockIdx.y * 32;
    int tx = threadIdx.x & 31, ty = threadIdx.x >> 5;
    #pragma unroll
    for (int i = 0; i < 4; i++)
        t[ty + i * 8][tx] = in[(long long)(r0 + ty + i * 8) * C + c0 + tx];
    __syncthreads();
    #pragma unroll
    for (int i = 0; i < 4; i++)
        out[(long long)(c0 + ty + i * 8) * R + r0 + tx] = t[tx][ty + i * 8];
}

// ---------------- embedding ---------------------------------------------------
__global__ void embed_kernel(const int* __restrict__ index,
                             const float* __restrict__ tok,
                             const float* __restrict__ pos) {
    int i = blockIdx.x * blockDim.x + threadIdx.x;
    if (i >= MROWS * DIM) return;
    int d = i % DIM;
    int bt = i / DIM;
    int t = bt % SEQ;
    g_x[i] = tok[(long long)index[bt] * DIM + d] + pos[(long long)t * DIM + d];
}

// ---------------- fp32 SGEMM (LM head only) ----------------------------------
#define BM 64
#define BN 64
#define BKK 16

__global__ __launch_bounds__(256)
void gemm_kernel(const float* __restrict__ A, const float* __restrict__ Bm,
                 const float* __restrict__ bias, float* __restrict__ C,
                 int M, int N, int K, int lda, int ldb, int ldc)
{
    int bm = blockIdx.y * BM;
    int bn = blockIdx.x * BN;
    __shared__ float As[BKK][BM + 1];
    __shared__ float Bs[BKK][BN + 1];

    int tid = threadIdx.x;
    int tx = tid & 15, ty = tid >> 4;
    float acc[4][4] = {};

    for (int k0 = 0; k0 < K; k0 += BKK) {
        #pragma unroll
        for (int i = 0; i < 4; i++) {
            int idx = tid + i * 256;
            int m  = idx >> 4;
            int kk = idx & 15;
            int gm = bm + m;
            float v = 0.f;
            if (gm < M) v = A[(long long)gm * lda + (k0 + kk)];
            As[kk][m] = v;
        }
        #pragma unroll
        for (int i = 0; i < 4; i++) {
            int idx = tid + i * 256;
            int kk = idx >> 6;
            int n  = idx & 63;
            int gn = bn + n;
            float v = 0.f;
            if (gn < N) v = Bm[(long long)(k0 + kk) * ldb + gn];
            Bs[kk][n] = v;
        }
        __syncthreads();
        #pragma unroll
        for (int kk = 0; kk < BKK; kk++) {
            float a[4], b[4];
            #pragma unroll
            for (int i = 0; i < 4; i++) a[i] = As[kk][ty * 4 + i];
            #pragma unroll
            for (int j = 0; j < 4; j++) b[j] = Bs[kk][tx * 4 + j];
            #pragma unroll
            for (int i = 0; i < 4; i++)
                #pragma unroll
                for (int j = 0; j < 4; j++)
                    acc[i][j] += a[i] * b[j];
        }
        __syncthreads();
    }

    #pragma unroll
    for (int i = 0; i < 4; i++) {
        int gm = bm + ty * 4 + i;
        if (gm >= M) continue;
        #pragma unroll
        for (int j = 0; j < 4; j++) {
            int gn = bn + tx * 4 + j;
            if (gn >= N) continue;
            float v = acc[i][j];
            if (bias) v += bias[gn];
            C[(long long)gm * ldc + gn] = v;
        }
    }
}

// ---------------- x = LayerNorm(x (+ y)) * g + b ----------------------------
__global__ __launch_bounds__(256)
void add_ln_kernel(float* __restrict__ x, const float* __restrict__ y,
                   const float* __restrict__ g, const float* __restrict__ bb) {
    int row = blockIdx.x;
    float* xr = x + (long long)row * DIM;
    const float* yr = y ? y + (long long)row * DIM : nullptr;
    __shared__ float s[DIM];
    __shared__ float red[256];
    int tid = threadIdx.x;

    float local = 0.f;
    #pragma unroll
    for (int i = 0; i < 4; i++) {
        int d = tid + i * 256;
        float v = xr[d];
        if (yr) v += yr[d];
        s[d] = v;
        local += v;
    }
    red[tid] = local; __syncthreads();
    for (int st = 128; st > 0; st >>= 1) {
        if (tid < st) red[tid] += red[tid + st];
        __syncthreads();
    }
    float mean = red[0] * (1.0f / DIM); __syncthreads();

    local = 0.f;
    #pragma unroll
    for (int i = 0; i < 4; i++) {
        float d2 = s[tid + i * 256] - mean;
        local += d2 * d2;
    }
    red[tid] = local; __syncthreads();
    for (int st = 128; st > 0; st >>= 1) {
        if (tid < st) red[tid] += red[tid + st];
        __syncthreads();
    }
    float inv = rsqrtf(red[0] * (1.0f / DIM) + 1e-5f);
    #pragma unroll
    for (int i = 0; i < 4; i++) {
        int d = tid + i * 256;
        xr[d] = (s[d] - mean) * inv * g[d] + bb[d];
    }
}

// ---------------- per-row NLL + loss -----------------------------------------
__global__ __launch_bounds__(128)
void nll_kernel(const float* __restrict__ logits, const int* __restrict__ targets) {
    int row = blockIdx.x;
    const float* p = logits + (long long)row * VOCABN;
    __shared__ float red[128];
    int tid = threadIdx.x;

    float v = (tid < VOCABN) ? p[tid] : -1e30f;
    red[tid] = v; __syncthreads();
    for (int s = 64; s > 0; s >>= 1) {
        if (tid < s) red[tid] = fmaxf(red[tid], red[tid + s]);
        __syncthreads();
    }
    float m = red[0]; __syncthreads();

    float e = (tid < VOCABN) ? expf(v - m) : 0.f;
    red[tid] = e; __syncthreads();
    for (int s = 64; s > 0; s >>= 1) {
        if (tid < s) red[tid] += red[tid + s];
        __syncthreads();
    }
    if (tid == 0) {
        float lse = m + logf(red[0]);
        g_nll[row] = lse - p[targets[row]];
    }
}

__global__ __launch_bounds__(256)
void loss_kernel(float* __restrict__ out) {
    __shared__ float red[256];
    int tid = threadIdx.x;
    float s = 0.f;
    for (int i = tid; i < MROWS; i += 256) s += g_nll[i];
    red[tid] = s; __syncthreads();
    for (int st = 128; st > 0; st >>= 1) {
        if (tid < st) red[tid] += red[tid + st];
        __syncthreads();
    }
    if (tid == 0) out[0] = red[0] * (1.0f / MROWS);
}

// ---------------- host-side launch helpers ----------------------------------
static float* sym(const void* s) {
    void* p = nullptr;
    cudaGetSymbolAddress(&p, s);
    return (float*)p;
}

static void run_gemm_tc(const float* A, const float* Bt, const float* bias,
                        float* C, int M, int N, int K, int lda, int ldb, int ldc,
                        int relu) {
    dim3 grid(N / TBN, M / TBM);
    gemm_mma<<<grid, 256>>>(A, Bt, bias, C, K, lda, ldb, ldc, relu);
}

extern "C" void kernel_launch(void* const* d_in, const int* in_sizes, int n_in,
                              void* d_out, int out_size) {
    const int*   index   = (const int*)  d_in[0];
    const int*   targets = (const int*)  d_in[1];
    const float* tok     = (const float*)d_in[2];
    const float* pos     = (const float*)d_in[3];
    const float* Wq      = (const float*)d_in[4];
    const float* Wk      = (const float*)d_in[5];
    const float* Wv      = (const float*)d_in[6];
    const float* Wo      = (const float*)d_in[7];
    const float* bo      = (const float*)d_in[8];
    const float* W1      = (const float*)d_in[9];
    const float* b1      = (const float*)d_in[10];
    const float* W2      = (const float*)d_in[11];
    const float* b2      = (const float*)d_in[12];
    const float* ln1g    = (const float*)d_in[13];
    const float* ln1b    = (const float*)d_in[14];
    const float* ln2g    = (const float*)d_in[15];
    const float* ln2b    = (const float*)d_in[16];
    const float* lnfg    = (const float*)d_in[17];
    const float* lnfb    = (const float*)d_in[18];
    const float* Wlm     = (const float*)d_in[19];
    const float* blm     = (const float*)d_in[20];
    float* out = (float*)d_out;

    float* x   = sym(g_x);
    float* q   = sym(g_q);
    float* k   = sym(g_k);
    float* v   = sym(g_v);
    float* o   = sym(g_o);
    float* y   = sym(g_y);
    float* hb  = sym(g_h);
    float* wqT = sym(g_wqT);
    float* wkT = sym(g_wkT);
    float* wvT = sym(g_wvT);
    float* woT = sym(g_woT);
    float* w1T = sym(g_w1T);
    float* w2T = sym(g_w2T);

    cudaFuncSetAttribute(flash_kernel,
                         cudaFuncAttributeMaxDynamicSharedMemorySize, FA_SMEM);

    // ---- weight transposes: W[K,N] -> Wt[N,K] (K-contiguous for mma B) -----
    {
        dim3 g1(HSZ / 32, DIM / 32, NL * NH);
        transpose_kernel<<<g1, 256>>>(Wq, wqT, DIM, HSZ);
        transpose_kernel<<<g1, 256>>>(Wk, wkT, DIM, HSZ);
        transpose_kernel<<<g1, 256>>>(Wv, wvT, DIM, HSZ);
        dim3 g2(DIM / 32, DIM / 32, NL);
        transpose_kernel<<<g2, 256>>>(Wo, woT, DIM, DIM);
        dim3 g3(FFD / 32, DIM / 32, NL);
        transpose_kernel<<<g3, 256>>>(W1, w1T, DIM, FFD);
        dim3 g4(DIM / 32, FFD / 32, NL);
        transpose_kernel<<<g4, 256>>>(W2, w2T, FFD, DIM);
    }

    // embedding
    {
        int n = MROWS * DIM;
        embed_kernel<<<(n + 255) / 256, 256>>>(index, tok, pos);
    }

    for (int l = 0; l < NL; l++) {
        const float* wqT_l = wqT + (long long)l * DIM * DIM;
        const float* wkT_l = wkT + (long long)l * DIM * DIM;
        const float* wvT_l = wvT + (long long)l * DIM * DIM;
        const float* woT_l = woT + (long long)l * DIM * DIM;
        const float* bo_l  = bo  + (long long)l * DIM;
        const float* w1T_l = w1T + (long long)l * DIM * FFD;
        const float* b1_l  = b1  + (long long)l * FFD;
        const float* w2T_l = w2T + (long long)l * FFD * DIM;
        const float* b2_l  = b2  + (long long)l * DIM;

        // q/k/v projections (tensor cores)
        run_gemm_tc(x, wqT_l, nullptr, q, MROWS, DIM, DIM, DIM, DIM, DIM, 0);
        run_gemm_tc(x, wkT_l, nullptr, k, MROWS, DIM, DIM, DIM, DIM, DIM, 0);
        run_gemm_tc(x, wvT_l, nullptr, v, MROWS, DIM, DIM, DIM, DIM, DIM, 0);

        // fused causal attention -> g_o
        {
            dim3 grid(SEQ / 64, BATCH * NH);
            flash_kernel<<<grid, 128, FA_SMEM>>>();
        }

        // output projection + residual LN
        run_gemm_tc(o, woT_l, bo_l, y, MROWS, DIM, DIM, DIM, DIM, DIM, 0);
        add_ln_kernel<<<MROWS, 256>>>(x, y, ln1g + (long long)l * DIM,
                                            ln1b + (long long)l * DIM);

        // feed-forward + residual LN
        run_gemm_tc(x, w1T_l, b1_l, hb, MROWS, FFD, DIM, DIM, DIM, FFD, 1);
        run_gemm_tc(hb, w2T_l, b2_l, y, MROWS, DIM, FFD, FFD, FFD, DIM, 0);
        add_ln_kernel<<<MROWS, 256>>>(x, y, ln2g + (long long)l * DIM,
                                            ln2b + (long long)l * DIM);
    }

    // final LN (no residual)
    add_ln_kernel<<<MROWS, 256>>>(x, nullptr, lnfg, lnfb);

    // logits = xf @ Wlm + blm (N=96, fp32 path, negligible flops)
    {
        dim3 grid((VOCABN + BN - 1) / BN, MROWS / BM);
        gemm_kernel<<<grid, 256>>>(x, Wlm, blm, out,
                                   MROWS, VOCABN, DIM, DIM, VOCABN, VOCABN);
    }

    // loss
    nll_kernel<<<MROWS, 128>>>(out, targets);
    if (out_size > MROWS * VOCABN) {
        loss_kernel<<<1, 256>>>(out + (long long)MROWS * VOCABN);
    }
}

// round 5
// speedup vs baseline: 3.3956x; 1.0765x over previous
#include <cuda_runtime.h>
#include <math.h>
#include <stdint.h>

#define VOCABN 96
#define DIM 1024
#define NH 16
#define HSZ 64
#define NL 8
#define BATCH 8
#define SEQ 1024
#define FFD 4096
#define MROWS (BATCH*SEQ)   // 8192
#define QKVLD (3*DIM)       // fused qkv row stride

// ---------------- scratch (device globals; no allocations allowed) ----------
__device__ float g_x[MROWS*DIM];
__device__ float g_qkv[(long long)MROWS*QKVLD];
__device__ float g_o[MROWS*DIM];
__device__ float g_y[MROWS*DIM];
__device__ float g_h[(long long)MROWS*FFD];
__device__ float g_wqkvT[(long long)NL*3*DIM*DIM];
__device__ float g_woT[NL*DIM*DIM];
__device__ float g_w1T[(long long)NL*DIM*FFD];
__device__ float g_w2T[(long long)NL*FFD*DIM];
__device__ float g_nll[MROWS];

// ======================= TF32 mma.sync helpers (sm_80+ portable) ============
__device__ __forceinline__ uint32_t f2tf32(float f) {
    uint32_t r;
    asm("cvt.rna.tf32.f32 %0, %1;" : "=r"(r) : "f"(f));
    return r;
}

__device__ __forceinline__ float f2tf32f(float f) {
    return __uint_as_float(f2tf32(f));
}

__device__ __forceinline__ void mma_tf32(float* c, const uint32_t* a, const uint32_t* b) {
    asm volatile(
        "mma.sync.aligned.m16n8k8.row.col.f32.tf32.tf32.f32 "
        "{%0,%1,%2,%3}, {%4,%5,%6,%7}, {%8,%9}, {%0,%1,%2,%3};"
        : "+f"(c[0]), "+f"(c[1]), "+f"(c[2]), "+f"(c[3])
        : "r"(a[0]), "r"(a[1]), "r"(a[2]), "r"(a[3]),
          "r"(b[0]), "r"(b[1]));
}

__device__ __forceinline__ uint32_t smem_u32_of(const void* p) {
    uint32_t a;
    asm("{ .reg .u64 t; cvta.to.shared.u64 t, %1; cvt.u32.u64 %0, t; }"
        : "=r"(a) : "l"(p));
    return a;
}

__device__ __forceinline__ void cp16(uint32_t dst, const void* src) {
    asm volatile("cp.async.cg.shared.global [%0], [%1], 16;"
                 :: "r"(dst), "l"(src) : "memory");
}

// ============ TF32 tensor GEMM: C[M,N] = A[M,K] @ B^T  (B stored [N,K]) =====
// CTA tile 128x128x32, 256 threads = 8 warps (2m x 4n), warp tile 64x32.
// cp.async double-buffered smem pipeline; operands pre-rounded to tf32.
#define TBM 128
#define TBN 128
#define TBK 32
#define SPAD 36           // smem row stride: bank = (4g+tg)%32, conflict-free
#define GBUF (128*SPAD)   // floats per tile (A or B)
#define GSM_BYTES (4*GBUF*4)  // 2 bufs x (A+B) = 73728 bytes

__global__ void __launch_bounds__(256, 2)
gemm_mma(const float* __restrict__ A, const float* __restrict__ B,
         const float* __restrict__ bias, float* __restrict__ C,
         int K, int lda, int ldb, int ldc, int relu)
{
    extern __shared__ float sm[];
    const int tid  = threadIdx.x;
    const int wid  = tid >> 5;
    const int lane = tid & 31;
    const int g    = lane >> 2;
    const int tg   = lane & 3;
    const int wm   = wid >> 2;
    const int wn   = wid & 3;

    const int bm = blockIdx.y * TBM;
    const int bn = blockIdx.x * TBN;

    const int r = tid >> 1;
    const int h = (tid & 1) * 16;
    const int rowoff = r * SPAD + h;

    const uint32_t smb = smem_u32_of(sm);
    const float* ga = A + (size_t)(bm + r) * lda + h;
    const float* gb = B + (size_t)(bn + r) * ldb + h;

    float acc[4][4][4] = {};
    const int KT = K / TBK;

    auto issue = [&](int kt, int buf) {
        const float* pa = ga + (size_t)kt * TBK;
        const float* pb = gb + (size_t)kt * TBK;
        uint32_t da = smb + (uint32_t)(buf * 2 * GBUF + rowoff) * 4;
        uint32_t db = da + GBUF * 4;
        #pragma unroll
        for (int c = 0; c < 4; c++) {
            cp16(da + c * 16, pa + 4 * c);
            cp16(db + c * 16, pb + 4 * c);
        }
        asm volatile("cp.async.commit_group;" ::: "memory");
    };

    issue(0, 0);

    int buf = 0;
    for (int kt = 0; kt < KT; kt++) {
        asm volatile("cp.async.wait_group 0;" ::: "memory");
        __syncthreads();
        if (kt + 1 < KT) issue(kt + 1, buf ^ 1);

        const float* As = sm + buf * 2 * GBUF;
        const float* Bs = As + GBUF;

        #pragma unroll
        for (int ks = 0; ks < 4; ks++) {
            const int k0 = ks * 8;
            uint32_t af[4][4], bf[4][2];
            #pragma unroll
            for (int i = 0; i < 4; i++) {
                const int m0 = wm * 64 + i * 16;
                af[i][0] = __float_as_uint(As[(m0 + g    ) * SPAD + k0 + tg    ]);
                af[i][1] = __float_as_uint(As[(m0 + g + 8) * SPAD + k0 + tg    ]);
                af[i][2] = __float_as_uint(As[(m0 + g    ) * SPAD + k0 + tg + 4]);
                af[i][3] = __float_as_uint(As[(m0 + g + 8) * SPAD + k0 + tg + 4]);
            }
            #pragma unroll
            for (int j = 0; j < 4; j++) {
                const int n0 = wn * 32 + j * 8;
                bf[j][0] = __float_as_uint(Bs[(n0 + g) * SPAD + k0 + tg    ]);
                bf[j][1] = __float_as_uint(Bs[(n0 + g) * SPAD + k0 + tg + 4]);
            }
            #pragma unroll
            for (int i = 0; i < 4; i++)
                #pragma unroll
                for (int j = 0; j < 4; j++)
                    mma_tf32(acc[i][j], af[i], bf[j]);
        }
        buf ^= 1;
    }

    // epilogue: bias + relu + tf32 rounding (outputs feed tensor GEMMs/flash)
    #pragma unroll
    for (int i = 0; i < 4; i++) {
        const int m0 = bm + wm * 64 + i * 16 + g;
        #pragma unroll
        for (int j = 0; j < 4; j++) {
            const int n0 = bn + wn * 32 + j * 8 + tg * 2;
            float2 v0 = make_float2(acc[i][j][0], acc[i][j][1]);
            float2 v1 = make_float2(acc[i][j][2], acc[i][j][3]);
            if (bias) {
                float2 bv = *(const float2*)(bias + n0);
                v0.x += bv.x; v0.y += bv.y;
                v1.x += bv.x; v1.y += bv.y;
            }
            if (relu) {
                v0.x = fmaxf(v0.x, 0.f); v0.y = fmaxf(v0.y, 0.f);
                v1.x = fmaxf(v1.x, 0.f); v1.y = fmaxf(v1.y, 0.f);
            }
            v0.x = f2tf32f(v0.x); v0.y = f2tf32f(v0.y);
            v1.x = f2tf32f(v1.x); v1.y = f2tf32f(v1.y);
            *(float2*)(C + (size_t)m0 * ldc + n0)       = v0;
            *(float2*)(C + (size_t)(m0 + 8) * ldc + n0) = v1;
        }
    }
}

// ============ Flash attention (causal, online softmax, TF32 mma) ============
// grid = (16 q-tiles, B*NH). block = 128 threads (4 warps, 16 q-rows each).
// Q/K/V read from fused g_qkv (stride QKVLD), already tf32-rounded.
#define FPAD 68
#define FA_SMEM ((3*64*FPAD + 4*16*FPAD) * 4)   // 69632 bytes

__global__ void __launch_bounds__(128, 3)
flash_kernel()
{
    extern __shared__ float sm[];
    float* Qs = sm;                  // [64][FPAD]
    float* Ks = sm + 64 * FPAD;      // [64][FPAD]
    float* Vs = sm + 2 * 64 * FPAD;  // [64][FPAD]
    float* Ps = sm + 3 * 64 * FPAD;  // [4][16][FPAD]

    const int bh = blockIdx.y;
    const int b = bh >> 4, hh = bh & 15;
    const int qt = gridDim.x - 1 - blockIdx.x;   // heavy blocks first
    const int tid = threadIdx.x;
    const int wid = tid >> 5, lane = tid & 31;
    const int g = lane >> 2, tg = lane & 3;

    const float* Qg = g_qkv + ((size_t)b * SEQ + qt * 64) * QKVLD + hh * HSZ;
    const float* Kg = g_qkv + (size_t)b * SEQ * QKVLD + DIM + hh * HSZ;
    const float* Vg = g_qkv + (size_t)b * SEQ * QKVLD + 2 * DIM + hh * HSZ;

    // load Q tile (already tf32-rounded)
    {
        const int r = tid >> 1, c0 = (tid & 1) * 32;
        const float* src = Qg + (size_t)r * QKVLD + c0;
        float* dst = Qs + r * FPAD + c0;
        #pragma unroll
        for (int c = 0; c < 32; c += 4)
            *(float4*)(dst + c) = *(const float4*)(src + c);
    }

    float m0 = -1e30f, m1 = -1e30f, l0 = 0.f, l1 = 0.f;
    float oacc[8][4];
    #pragma unroll
    for (int nb = 0; nb < 8; nb++)
        #pragma unroll
        for (int e = 0; e < 4; e++) oacc[nb][e] = 0.f;

    float* Pw = Ps + wid * 16 * FPAD;
    const float* qb = Qs + (wid * 16) * FPAD;
    const int row0 = qt * 64 + wid * 16 + g;

    for (int kt = 0; kt <= qt; kt++) {
        __syncthreads();
        {
            const int r = tid >> 1, c0 = (tid & 1) * 32;
            const float* ksrc = Kg + ((size_t)(kt * 64 + r)) * QKVLD + c0;
            const float* vsrc = Vg + ((size_t)(kt * 64 + r)) * QKVLD + c0;
            float* kdst = Ks + r * FPAD + c0;
            float* vdst = Vs + r * FPAD + c0;
            #pragma unroll
            for (int c = 0; c < 32; c += 4) {
                *(float4*)(kdst + c) = *(const float4*)(ksrc + c);
                *(float4*)(vdst + c) = *(const float4*)(vsrc + c);
            }
        }
        __syncthreads();

        // S = Q @ K^T
        float sacc[8][4];
        #pragma unroll
        for (int nb = 0; nb < 8; nb++)
            #pragma unroll
            for (int e = 0; e < 4; e++) sacc[nb][e] = 0.f;

        #pragma unroll
        for (int ks = 0; ks < 8; ks++) {
            const int k0 = ks * 8;
            uint32_t af[4];
            af[0] = __float_as_uint(qb[(g    ) * FPAD + k0 + tg    ]);
            af[1] = __float_as_uint(qb[(g + 8) * FPAD + k0 + tg    ]);
            af[2] = __float_as_uint(qb[(g    ) * FPAD + k0 + tg + 4]);
            af[3] = __float_as_uint(qb[(g + 8) * FPAD + k0 + tg + 4]);
            #pragma unroll
            for (int nb = 0; nb < 8; nb++) {
                uint32_t bf[2];
                bf[0] = __float_as_uint(Ks[(nb * 8 + g) * FPAD + k0 + tg    ]);
                bf[1] = __float_as_uint(Ks[(nb * 8 + g) * FPAD + k0 + tg + 4]);
                mma_tf32(sacc[nb], af, bf);
            }
        }

        const float scale = 0.125f;
        #pragma unroll
        for (int nb = 0; nb < 8; nb++)
            #pragma unroll
            for (int e = 0; e < 4; e++) sacc[nb][e] *= scale;
        if (kt == qt) {
            #pragma unroll
            for (int nb = 0; nb < 8; nb++) {
                const int col = kt * 64 + nb * 8 + tg * 2;
                if (col     > row0) sacc[nb][0] = -1e9f;
                if (col + 1 > row0) sacc[nb][1] = -1e9f;
                if (col     > row0 + 8) sacc[nb][2] = -1e9f;
                if (col + 1 > row0 + 8) sacc[nb][3] = -1e9f;
            }
        }

        float tmax0 = -1e30f, tmax1 = -1e30f;
        #pragma unroll
        for (int nb = 0; nb < 8; nb++) {
            tmax0 = fmaxf(tmax0, fmaxf(sacc[nb][0], sacc[nb][1]));
            tmax1 = fmaxf(tmax1, fmaxf(sacc[nb][2], sacc[nb][3]));
        }
        tmax0 = fmaxf(tmax0, __shfl_xor_sync(0xffffffff, tmax0, 1));
        tmax0 = fmaxf(tmax0, __shfl_xor_sync(0xffffffff, tmax0, 2));
        tmax1 = fmaxf(tmax1, __shfl_xor_sync(0xffffffff, tmax1, 1));
        tmax1 = fmaxf(tmax1, __shfl_xor_sync(0xffffffff, tmax1, 2));

        const float mn0 = fmaxf(m0, tmax0);
        const float mn1 = fmaxf(m1, tmax1);
        const float a0 = __expf(m0 - mn0);
        const float a1 = __expf(m1 - mn1);
        m0 = mn0; m1 = mn1;

        float sum0 = 0.f, sum1 = 0.f;
        #pragma unroll
        for (int nb = 0; nb < 8; nb++) {
            float p00 = __expf(sacc[nb][0] - mn0);
            float p01 = __expf(sacc[nb][1] - mn0);
            float p10 = __expf(sacc[nb][2] - mn1);
            float p11 = __expf(sacc[nb][3] - mn1);
            sum0 += p00 + p01;
            sum1 += p10 + p11;
            float* p0 = Pw + g * FPAD + nb * 8 + tg * 2;
            float* p1 = Pw + (g + 8) * FPAD + nb * 8 + tg * 2;
            p0[0] = f2tf32f(p00); p0[1] = f2tf32f(p01);
            p1[0] = f2tf32f(p10); p1[1] = f2tf32f(p11);
        }
        sum0 += __shfl_xor_sync(0xffffffff, sum0, 1);
        sum0 += __shfl_xor_sync(0xffffffff, sum0, 2);
        sum1 += __shfl_xor_sync(0xffffffff, sum1, 1);
        sum1 += __shfl_xor_sync(0xffffffff, sum1, 2);
        l0 = l0 * a0 + sum0;
        l1 = l1 * a1 + sum1;

        #pragma unroll
        for (int nb = 0; nb < 8; nb++) {
            oacc[nb][0] *= a0; oacc[nb][1] *= a0;
            oacc[nb][2] *= a1; oacc[nb][3] *= a1;
        }

        __syncwarp();

        #pragma unroll
        for (int kb = 0; kb < 8; kb++) {
            const int k0 = kb * 8;
            uint32_t pf[4];
            pf[0] = __float_as_uint(Pw[(g    ) * FPAD + k0 + tg    ]);
            pf[1] = __float_as_uint(Pw[(g + 8) * FPAD + k0 + tg    ]);
            pf[2] = __float_as_uint(Pw[(g    ) * FPAD + k0 + tg + 4]);
            pf[3] = __float_as_uint(Pw[(g + 8) * FPAD + k0 + tg + 4]);
            #pragma unroll
            for (int nb = 0; nb < 8; nb++) {
                uint32_t vf[2];
                vf[0] = __float_as_uint(Vs[(k0 + tg    ) * FPAD + nb * 8 + g]);
                vf[1] = __float_as_uint(Vs[(k0 + tg + 4) * FPAD + nb * 8 + g]);
                mma_tf32(oacc[nb], pf, vf);
            }
        }
    }

    const float inv0 = 1.f / l0;
    const float inv1 = 1.f / l1;
    float* orow0 = g_o + ((size_t)b * SEQ + row0    ) * DIM + hh * HSZ;
    float* orow1 = g_o + ((size_t)b * SEQ + row0 + 8) * DIM + hh * HSZ;
    #pragma unroll
    for (int nb = 0; nb < 8; nb++) {
        const int c = nb * 8 + tg * 2;
        *(float2*)(orow0 + c) = make_float2(f2tf32f(oacc[nb][0] * inv0),
                                            f2tf32f(oacc[nb][1] * inv0));
        *(float2*)(orow1 + c) = make_float2(f2tf32f(oacc[nb][2] * inv1),
                                            f2tf32f(oacc[nb][3] * inv1));
    }
}

// ------- tiled transpose + tf32 round; out offset = (z/zdiv)*s1 + (z%zdiv)*s2
__global__ __launch_bounds__(256)
void transpose_kernel(const float* __restrict__ in, float* __restrict__ out,
                      int R, int C, int zdiv, long long s1, long long s2) {
    __shared__ float t[32][33];
    long long z = blockIdx.z;
    in  += z * (long long)R * C;
    out += (z / zdiv) * s1 + (z % zdiv) * s2;
    int c0 = blockIdx.x * 32, r0 = blockIdx.y * 32;
    int tx = threadIdx.x & 31, ty = threadIdx.x >> 5;
    #pragma unroll
    for (int i = 0; i < 4; i++)
        t[ty + i * 8][tx] = in[(long long)(r0 + ty + i * 8) * C + c0 + tx];
    __syncthreads();
    #pragma unroll
    for (int i = 0; i < 4; i++)
        out[(long long)(c0 + ty + i * 8) * R + r0 + tx] = f2tf32f(t[tx][ty + i * 8]);
}

// ---------------- embedding (tf32-rounded output) ----------------------------
__global__ void embed_kernel(const int* __restrict__ index,
                             const float* __restrict__ tok,
                             const float* __restrict__ pos) {
    int i = blockIdx.x * blockDim.x + threadIdx.x;
    if (i >= MROWS * DIM) return;
    int d = i % DIM;
    int bt = i / DIM;
    int t = bt % SEQ;
    g_x[i] = f2tf32f(tok[(long long)index[bt] * DIM + d] + pos[(long long)t * DIM + d]);
}

// ---------------- fp32 SGEMM (LM head only) ----------------------------------
#define BM 64
#define BN 64
#define BKK 16

__global__ __launch_bounds__(256)
void gemm_kernel(const float* __restrict__ A, const float* __restrict__ Bm,
                 const float* __restrict__ bias, float* __restrict__ C,
                 int M, int N, int K, int lda, int ldb, int ldc)
{
    int bm = blockIdx.y * BM;
    int bn = blockIdx.x * BN;
    __shared__ float As[BKK][BM + 1];
    __shared__ float Bs[BKK][BN + 1];

    int tid = threadIdx.x;
    int tx = tid & 15, ty = tid >> 4;
    float acc[4][4] = {};

    for (int k0 = 0; k0 < K; k0 += BKK) {
        #pragma unroll
        for (int i = 0; i < 4; i++) {
            int idx = tid + i * 256;
            int m  = idx >> 4;
            int kk = idx & 15;
            int gm = bm + m;
            float v = 0.f;
            if (gm < M) v = A[(long long)gm * lda + (k0 + kk)];
            As[kk][m] = v;
        }
        #pragma unroll
        for (int i = 0; i < 4; i++) {
            int idx = tid + i * 256;
            int kk = idx >> 6;
            int n  = idx & 63;
            int gn = bn + n;
            float v = 0.f;
            if (gn < N) v = Bm[(long long)(k0 + kk) * ldb + gn];
            Bs[kk][n] = v;
        }
        __syncthreads();
        #pragma unroll
        for (int kk = 0; kk < BKK; kk++) {
            float a[4], b[4];
            #pragma unroll
            for (int i = 0; i < 4; i++) a[i] = As[kk][ty * 4 + i];
            #pragma unroll
            for (int j = 0; j < 4; j++) b[j] = Bs[kk][tx * 4 + j];
            #pragma unroll
            for (int i = 0; i < 4; i++)
                #pragma unroll
                for (int j = 0; j < 4; j++)
                    acc[i][j] += a[i] * b[j];
        }
        __syncthreads();
    }

    #pragma unroll
    for (int i = 0; i < 4; i++) {
        int gm = bm + ty * 4 + i;
        if (gm >= M) continue;
        #pragma unroll
        for (int j = 0; j < 4; j++) {
            int gn = bn + tx * 4 + j;
            if (gn >= N) continue;
            float v = acc[i][j];
            if (bias) v += bias[gn];
            C[(long long)gm * ldc + gn] = v;
        }
    }
}

// -------- x = LayerNorm(x (+ y)) * g + b, optional tf32-round of output ------
__global__ __launch_bounds__(256)
void add_ln_kernel(float* __restrict__ x, const float* __restrict__ y,
                   const float* __restrict__ g, const float* __restrict__ bb,
                   int rnd) {
    int row = blockIdx.x;
    float* xr = x + (long long)row * DIM;
    const float* yr = y ? y + (long long)row * DIM : nullptr;
    __shared__ float s[DIM];
    __shared__ float red[256];
    int tid = threadIdx.x;

    float local = 0.f;
    #pragma unroll
    for (int i = 0; i < 4; i++) {
        int d = tid + i * 256;
        float v = xr[d];
        if (yr) v += yr[d];
        s[d] = v;
        local += v;
    }
    red[tid] = local; __syncthreads();
    for (int st = 128; st > 0; st >>= 1) {
        if (tid < st) red[tid] += red[tid + st];
        __syncthreads();
    }
    float mean = red[0] * (1.0f / DIM); __syncthreads();

    local = 0.f;
    #pragma unroll
    for (int i = 0; i < 4; i++) {
        float d2 = s[tid + i * 256] - mean;
        local += d2 * d2;
    }
    red[tid] = local; __syncthreads();
    for (int st = 128; st > 0; st >>= 1) {
        if (tid < st) red[tid] += red[tid + st];
        __syncthreads();
    }
    float inv = rsqrtf(red[0] * (1.0f / DIM) + 1e-5f);
    #pragma unroll
    for (int i = 0; i < 4; i++) {
        int d = tid + i * 256;
        float v = (s[d] - mean) * inv * g[d] + bb[d];
        xr[d] = rnd ? f2tf32f(v) : v;
    }
}

// ---------------- per-row NLL + loss -----------------------------------------
__global__ __launch_bounds__(128)
void nll_kernel(const float* __restrict__ logits, const int* __restrict__ targets) {
    int row = blockIdx.x;
    const float* p = logits + (long long)row * VOCABN;
    __shared__ float red[128];
    int tid = threadIdx.x;

    float v = (tid < VOCABN) ? p[tid] : -1e30f;
    red[tid] = v; __syncthreads();
    for (int s = 64; s > 0; s >>= 1) {
        if (tid < s) red[tid] = fmaxf(red[tid], red[tid + s]);
        __syncthreads();
    }
    float m = red[0]; __syncthreads();

    float e = (tid < VOCABN) ? expf(v - m) : 0.f;
    red[tid] = e; __syncthreads();
    for (int s = 64; s > 0; s >>= 1) {
        if (tid < s) red[tid] += red[tid + s];
        __syncthreads();
    }
    if (tid == 0) {
        float lse = m + logf(red[0]);
        g_nll[row] = lse - p[targets[row]];
    }
}

__global__ __launch_bounds__(256)
void loss_kernel(float* __restrict__ out) {
    __shared__ float red[256];
    int tid = threadIdx.x;
    float s = 0.f;
    for (int i = tid; i < MROWS; i += 256) s += g_nll[i];
    red[tid] = s; __syncthreads();
    for (int st = 128; st > 0; st >>= 1) {
        if (tid < st) red[tid] += red[tid + st];
        __syncthreads();
    }
    if (tid == 0) out[0] = red[0] * (1.0f / MROWS);
}

// ---------------- host-side launch helpers ----------------------------------
static float* sym(const void* s) {
    void* p = nullptr;
    cudaGetSymbolAddress(&p, s);
    return (float*)p;
}

static void run_gemm_tc(const float* A, const float* Bt, const float* bias,
                        float* C, int M, int N, int K, int lda, int ldb, int ldc,
                        int relu) {
    dim3 grid(N / TBN, M / TBM);
    gemm_mma<<<grid, 256, GSM_BYTES>>>(A, Bt, bias, C, K, lda, ldb, ldc, relu);
}

extern "C" void kernel_launch(void* const* d_in, const int* in_sizes, int n_in,
                              void* d_out, int out_size) {
    const int*   index   = (const int*)  d_in[0];
    const int*   targets = (const int*)  d_in[1];
    const float* tok     = (const float*)d_in[2];
    const float* pos     = (const float*)d_in[3];
    const float* Wq      = (const float*)d_in[4];
    const float* Wk      = (const float*)d_in[5];
    const float* Wv      = (const float*)d_in[6];
    const float* Wo      = (const float*)d_in[7];
    const float* bo      = (const float*)d_in[8];
    const float* W1      = (const float*)d_in[9];
    const float* b1      = (const float*)d_in[10];
    const float* W2      = (const float*)d_in[11];
    const float* b2      = (const float*)d_in[12];
    const float* ln1g    = (const float*)d_in[13];
    const float* ln1b    = (const float*)d_in[14];
    const float* ln2g    = (const float*)d_in[15];
    const float* ln2b    = (const float*)d_in[16];
    const float* lnfg    = (const float*)d_in[17];
    const float* lnfb    = (const float*)d_in[18];
    const float* Wlm     = (const float*)d_in[19];
    const float* blm     = (const float*)d_in[20];
    float* out = (float*)d_out;

    float* x    = sym(g_x);
    float* qkv  = sym(g_qkv);
    float* o    = sym(g_o);
    float* y    = sym(g_y);
    float* hb   = sym(g_h);
    float* wqkvT= sym(g_wqkvT);
    float* woT  = sym(g_woT);
    float* w1T  = sym(g_w1T);
    float* w2T  = sym(g_w2T);

    static int attr_done = 0;
    if (!attr_done) {
        cudaFuncSetAttribute(flash_kernel,
                             cudaFuncAttributeMaxDynamicSharedMemorySize, FA_SMEM);
        cudaFuncSetAttribute(gemm_mma,
                             cudaFuncAttributeMaxDynamicSharedMemorySize, GSM_BYTES);
        attr_done = 1;
    }

    // ---- weight transposes -> [N,K] tf32-rounded ---------------------------
    {
        const long long DD = (long long)DIM * DIM;
        dim3 g1(HSZ / 32, DIM / 32, NL * NH);
        // Wq/Wk/Wv: z = l*NH + h; out = wqkvT + l*3DD + part*DD + h*HSZ*DIM
        transpose_kernel<<<g1, 256>>>(Wq, wqkvT,          DIM, HSZ, NH, 3 * DD, (long long)HSZ * DIM);
        transpose_kernel<<<g1, 256>>>(Wk, wqkvT + DD,     DIM, HSZ, NH, 3 * DD, (long long)HSZ * DIM);
        transpose_kernel<<<g1, 256>>>(Wv, wqkvT + 2 * DD, DIM, HSZ, NH, 3 * DD, (long long)HSZ * DIM);
        dim3 g2(DIM / 32, DIM / 32, NL);
        transpose_kernel<<<g2, 256>>>(Wo, woT, DIM, DIM, 1, DD, 0);
        dim3 g3(FFD / 32, DIM / 32, NL);
        transpose_kernel<<<g3, 256>>>(W1, w1T, DIM, FFD, 1, (long long)DIM * FFD, 0);
        dim3 g4(DIM / 32, FFD / 32, NL);
        transpose_kernel<<<g4, 256>>>(W2, w2T, FFD, DIM, 1, (long long)FFD * DIM, 0);
    }

    // embedding
    {
        int n = MROWS * DIM;
        embed_kernel<<<(n + 255) / 256, 256>>>(index, tok, pos);
    }

    for (int l = 0; l < NL; l++) {
        const float* wqkvT_l = wqkvT + (long long)l * 3 * DIM * DIM;
        const float* woT_l   = woT   + (long long)l * DIM * DIM;
        const float* bo_l    = bo    + (long long)l * DIM;
        const float* w1T_l   = w1T   + (long long)l * DIM * FFD;
        const float* b1_l    = b1    + (long long)l * FFD;
        const float* w2T_l   = w2T   + (long long)l * FFD * DIM;
        const float* b2_l    = b2    + (long long)l * DIM;

        // fused qkv projection: [8192, 3072]
        run_gemm_tc(x, wqkvT_l, nullptr, qkv, MROWS, QKVLD, DIM, DIM, DIM, QKVLD, 0);

        // fused causal attention -> g_o
        {
            dim3 grid(SEQ / 64, BATCH * NH);
            flash_kernel<<<grid, 128, FA_SMEM>>>();
        }

        // output projection + residual LN
        run_gemm_tc(o, woT_l, bo_l, y, MROWS, DIM, DIM, DIM, DIM, DIM, 0);
        add_ln_kernel<<<MROWS, 256>>>(x, y, ln1g + (long long)l * DIM,
                                            ln1b + (long long)l * DIM, 1);

        // feed-forward + residual LN
        run_gemm_tc(x, w1T_l, b1_l, hb, MROWS, FFD, DIM, DIM, DIM, FFD, 1);
        run_gemm_tc(hb, w2T_l, b2_l, y, MROWS, DIM, FFD, FFD, FFD, DIM, 0);
        add_ln_kernel<<<MROWS, 256>>>(x, y, ln2g + (long long)l * DIM,
                                            ln2b + (long long)l * DIM, 1);
    }

    // final LN (no residual, keep fp32 — feeds fp32 LM head only)
    add_ln_kernel<<<MROWS, 256>>>(x, nullptr, lnfg, lnfb, 0);

    // logits = xf @ Wlm + blm (N=96, fp32 path)
    {
        dim3 grid((VOCABN + BN - 1) / BN, MROWS / BM);
        gemm_kernel<<<grid, 256>>>(x, Wlm, blm, out,
                                   MROWS, VOCABN, DIM, DIM, VOCABN, VOCABN);
    }

    // loss
    nll_kernel<<<MROWS, 128>>>(out, targets);
    if (out_size > MROWS * VOCABN) {
        loss_kernel<<<1, 256>>>(out + (long long)MROWS * VOCABN);
    }
}